// round 7
// baseline (speedup 1.0000x reference)
#include <cuda_runtime.h>
#include <cuda_bf16.h>
#include <math.h>
#include <stdint.h>

#define NN   100000
#define EE   1600000
#define ET   1700000      // EE + NN self loops
#define FIN  512
#define HD   64           // H1*D1
#define H1   8
#define D1   8
#define CC   16
#define NB   ((NN + 255) / 256)   // 391 scan blocks

// ---------------- scratch (static device memory; no allocations) ----------------
__device__ int   g_flag;
__device__ int   g_src[ET];
__device__ int   g_dst[ET];
__device__ int   g_col[ET];
__device__ int   g_counts[NN];
__device__ int   g_cursor[NN];
__device__ int   g_rowptr[NN + 1];
__device__ int   g_bsum[NB];
__device__ int   g_boff[NB];
__device__ __nv_bfloat16 g_wbhi[HD * FIN];   // W1^T bf16 hi, [n][k]
__device__ __nv_bfloat16 g_wblo[HD * FIN];   // W1^T bf16 lo, [n][k]
__device__ float g_h1[(size_t)NN * HD];
__device__ float g_h1act[(size_t)NN * HD];
__device__ float g_es1[(size_t)NN * H1];
__device__ float g_ed1[(size_t)NN * H1];
__device__ float g_h2[(size_t)NN * CC];
__device__ float g_es2[NN];
__device__ float g_ed2[NN];

// ---------------- init: zero counts + dtype detect + W1 bf16 hi/lo convert ----------------
__global__ __launch_bounds__(256) void init_kernel(const int* ei32, const float* __restrict__ W1) {
    int i = blockIdx.x * blockDim.x + threadIdx.x;
    if (i < NN) g_counts[i] = 0;
    if (i < HD * FIN) {                     // transpose-convert W1: out [n][k] = W1[k][n]
        int n = i >> 9, k = i & 511;
        float v = W1[(size_t)k * HD + n];
        __nv_bfloat16 h = __float2bfloat16_rn(v);
        g_wbhi[i] = h;
        g_wblo[i] = __float2bfloat16_rn(v - __bfloat162float(h));
    }
    if (blockIdx.x == 0 && threadIdx.x < 32) {
        int lane = threadIdx.x;
        int bad = 0;
        for (int j = lane; j < 256; j += 32) {
            int k = j * 6250;
            if (ei32[2 * k + 1] != 0) bad = 1;
        }
        unsigned b = __ballot_sync(0xffffffffu, bad);
        if (lane == 0) g_flag = (b == 0) ? 1 : 0;
    }
}

// ---------------- convert + histogram in one edge pass ----------------
__global__ __launch_bounds__(256) void convert_hist_kernel(const void* ei) {
    int e = blockIdx.x * blockDim.x + threadIdx.x;
    if (e >= ET) return;
    int s, d;
    if (e < EE) {
        if (g_flag) {
            const long long* p = (const long long*)ei;
            s = (int)p[e]; d = (int)p[EE + e];
        } else {
            const int* p = (const int*)ei;
            s = p[e]; d = p[EE + e];
        }
    } else {
        s = e - EE; d = e - EE;
    }
    g_src[e] = s; g_dst[e] = d;
    atomicAdd(&g_counts[d], 1);
}

// ---------------- parallel scan ----------------
__global__ __launch_bounds__(256) void scan_partial_kernel() {
    __shared__ int wsum[8];
    int t = threadIdx.x;
    int i = blockIdx.x * 256 + t;
    int c = (i < NN) ? g_counts[i] : 0;
    int v = c;
    #pragma unroll
    for (int off = 1; off < 32; off <<= 1) v += __shfl_xor_sync(0xffffffffu, v, off);
    if ((t & 31) == 0) wsum[t >> 5] = v;
    __syncthreads();
    if (t == 0) {
        int s = 0;
        #pragma unroll
        for (int w = 0; w < 8; w++) s += wsum[w];
        g_bsum[blockIdx.x] = s;
    }
}

__global__ __launch_bounds__(512) void scan_blocks_kernel() {
    __shared__ int sh[512];
    int t = threadIdx.x;
    sh[t] = (t < NB) ? g_bsum[t] : 0;
    __syncthreads();
    for (int off = 1; off < 512; off <<= 1) {
        int v = (t >= off) ? sh[t - off] : 0;
        __syncthreads();
        sh[t] += v;
        __syncthreads();
    }
    if (t < NB) g_boff[t] = (t == 0) ? 0 : sh[t - 1];
}

__global__ __launch_bounds__(256) void scan_apply_kernel() {
    __shared__ int woff[8];
    int t = threadIdx.x, lane = t & 31, wid = t >> 5;
    int i = blockIdx.x * 256 + t;
    int c = (i < NN) ? g_counts[i] : 0;
    int incl = c;
    #pragma unroll
    for (int off = 1; off < 32; off <<= 1) {
        int v = __shfl_up_sync(0xffffffffu, incl, off);
        if (lane >= off) incl += v;
    }
    if (lane == 31) woff[wid] = incl;
    __syncthreads();
    if (t == 0) {
        int run = 0;
        #pragma unroll
        for (int w = 0; w < 8; w++) { int v = woff[w]; woff[w] = run; run += v; }
    }
    __syncthreads();
    int excl = incl - c + woff[wid] + g_boff[blockIdx.x];
    if (i < NN) { g_rowptr[i] = excl; g_cursor[i] = excl; }
    if (i == NN - 1) g_rowptr[NN] = ET;
}

__global__ __launch_bounds__(256) void scatter_kernel() {
    int e = blockIdx.x * blockDim.x + threadIdx.x;
    if (e < ET) {
        int d = g_dst[e];
        int pos = atomicAdd(&g_cursor[d], 1);
        g_col[pos] = g_src[e];
    }
}

// ---------------- GEMM1: cp.async pipelined HMMA split-bf16 + fused es/ed ----------------
#define BKG   64                 // K per stage
#define STG   3                  // pipeline stages
#define APAD  68                 // fp32 stride per A row (272B)
#define G1_SMEM (STG * 128 * APAD * 4)

__device__ __forceinline__ void cp_async16(uint32_t saddr, const void* gptr) {
    asm volatile("cp.async.ca.shared.global [%0], [%1], 16;" :: "r"(saddr), "l"(gptr));
}
__device__ __forceinline__ void cp_commit() {
    asm volatile("cp.async.commit_group;");
}

__device__ __forceinline__ void cvt_pair(float vx, float vy, uint32_t& hi, uint32_t& lo) {
    asm("cvt.rn.bf16x2.f32 %0, %1, %2;" : "=r"(hi) : "f"(vy), "f"(vx));
    float h0 = __uint_as_float(hi << 16);
    float h1 = __uint_as_float(hi & 0xFFFF0000u);
    float r0 = vx - h0, r1 = vy - h1;
    asm("cvt.rn.bf16x2.f32 %0, %1, %2;" : "=r"(lo) : "f"(r1), "f"(r0));
}

__device__ __forceinline__ void mma16816(float* c, const uint32_t* a, uint32_t b0, uint32_t b1) {
    asm volatile(
        "mma.sync.aligned.m16n8k16.row.col.f32.bf16.bf16.f32 "
        "{%0,%1,%2,%3}, {%4,%5,%6,%7}, {%8,%9}, {%0,%1,%2,%3};"
        : "+f"(c[0]), "+f"(c[1]), "+f"(c[2]), "+f"(c[3])
        : "r"(a[0]), "r"(a[1]), "r"(a[2]), "r"(a[3]), "r"(b0), "r"(b1));
}

__global__ __launch_bounds__(256, 2) void gemm1_mma_kernel(const float* __restrict__ x,
                                                           const float* __restrict__ a1s,
                                                           const float* __restrict__ a1d) {
    extern __shared__ float sA[];           // [STG][128][APAD]
    uint32_t sbase;
    asm("{ .reg .u64 t; cvta.to.shared.u64 t, %1; cvt.u32.u64 %0, t; }" : "=r"(sbase) : "l"(sA));

    int tid = threadIdx.x;
    int wid = tid >> 5, lane = tid & 31;
    int g = lane >> 2, tc = lane & 3;
    int wm = wid & 3, wn = wid >> 2;
    int block_row = blockIdx.x * 128;
    int row_base = block_row + wm * 32;

    // A stage loader mapping: thread t copies 128B of one row
    int arow = tid >> 1;                    // 0..127
    int acol = (tid & 1) * 32;              // float offset within row (0 or 32)
    int grow = block_row + arow;
    bool row_ok = grow < NN;
    const float* gsrc = x + (size_t)grow * FIN + acol;

    float acc[2][4][4];
    #pragma unroll
    for (int mt = 0; mt < 2; mt++)
        #pragma unroll
        for (int nt = 0; nt < 4; nt++)
            #pragma unroll
            for (int q = 0; q < 4; q++) acc[mt][nt][q] = 0.f;

    // prologue: load stages 0..STG-2
    #pragma unroll
    for (int s = 0; s < STG - 1; s++) {
        uint32_t sa = sbase + ((s * 128 + arow) * APAD + acol) * 4;
        if (row_ok) {
            #pragma unroll
            for (int i = 0; i < 8; i++)
                cp_async16(sa + i * 16, gsrc + s * BKG + i * 4);
        } else {
            float4 z = make_float4(0.f, 0.f, 0.f, 0.f);
            #pragma unroll
            for (int i = 0; i < 8; i++)
                *(float4*)((char*)sA + (sa - sbase) + i * 16) = z;
        }
        cp_commit();
    }

    const int NSTEP = FIN / BKG;            // 8
    for (int step = 0; step < NSTEP; step++) {
        if (step < NSTEP - 1) {
            asm volatile("cp.async.wait_group 1;");
        } else {
            asm volatile("cp.async.wait_group 0;");
        }
        __syncthreads();
        int cur = step % STG;
        const float* sAc = sA + cur * 128 * APAD;

        #pragma unroll
        for (int ks = 0; ks < BKG / 16; ks++) {
            int kg = step * BKG + ks * 16;  // global k of this 16-step
            int kl = ks * 16 + tc * 2;      // local k in stage
            uint32_t ah[2][4], al[2][4];
            #pragma unroll
            for (int mt = 0; mt < 2; mt++) {
                int lr0 = wm * 32 + mt * 16 + g;
                int lr1 = lr0 + 8;
                float2 v0 = *(const float2*)(sAc + lr0 * APAD + kl);
                float2 v1 = *(const float2*)(sAc + lr1 * APAD + kl);
                float2 v2 = *(const float2*)(sAc + lr0 * APAD + kl + 8);
                float2 v3 = *(const float2*)(sAc + lr1 * APAD + kl + 8);
                cvt_pair(v0.x, v0.y, ah[mt][0], al[mt][0]);
                cvt_pair(v1.x, v1.y, ah[mt][1], al[mt][1]);
                cvt_pair(v2.x, v2.y, ah[mt][2], al[mt][2]);
                cvt_pair(v3.x, v3.y, ah[mt][3], al[mt][3]);
            }
            #pragma unroll
            for (int nt = 0; nt < 4; nt++) {
                int n = wn * 32 + nt * 8 + g;
                const __nv_bfloat16* ph = g_wbhi + (size_t)n * FIN + kg + tc * 2;
                const __nv_bfloat16* pl = g_wblo + (size_t)n * FIN + kg + tc * 2;
                uint32_t bh0 = *(const uint32_t*)ph;
                uint32_t bh1 = *(const uint32_t*)(ph + 8);
                uint32_t bl0 = *(const uint32_t*)pl;
                uint32_t bl1 = *(const uint32_t*)(pl + 8);
                #pragma unroll
                for (int mt = 0; mt < 2; mt++) {
                    mma16816(acc[mt][nt], ah[mt], bh0, bh1);
                    mma16816(acc[mt][nt], al[mt], bh0, bh1);
                    mma16816(acc[mt][nt], ah[mt], bl0, bl1);
                }
            }
        }
        __syncthreads();                    // everyone done with the stage we overwrite next
        int nxt = step + STG - 1;
        if (nxt < NSTEP) {
            int sbuf = nxt % STG;
            uint32_t sa = sbase + ((sbuf * 128 + arow) * APAD + acol) * 4;
            if (row_ok) {
                #pragma unroll
                for (int i = 0; i < 8; i++)
                    cp_async16(sa + i * 16, gsrc + nxt * BKG + i * 4);
            } else {
                float4 z = make_float4(0.f, 0.f, 0.f, 0.f);
                #pragma unroll
                for (int i = 0; i < 8; i++)
                    *(float4*)((char*)sA + (sa - sbase) + i * 16) = z;
            }
            cp_commit();
        }
    }

    // ---- epilogue: write h1, fused es/ed ----
    int col_base = wn * 32;
    #pragma unroll
    for (int mt = 0; mt < 2; mt++) {
        int r0 = row_base + mt * 16 + g;
        int r1 = r0 + 8;
        #pragma unroll
        for (int nt = 0; nt < 4; nt++) {
            int col = col_base + nt * 8 + tc * 2;
            float* c = acc[mt][nt];
            if (r0 < NN) *(float2*)(g_h1 + (size_t)r0 * HD + col) = make_float2(c[0], c[1]);
            if (r1 < NN) *(float2*)(g_h1 + (size_t)r1 * HD + col) = make_float2(c[2], c[3]);
            int head = (col_base >> 3) + nt;
            float as0 = a1s[head * 8 + tc * 2], as1 = a1s[head * 8 + tc * 2 + 1];
            float ad0 = a1d[head * 8 + tc * 2], ad1 = a1d[head * 8 + tc * 2 + 1];
            float es_a = c[0] * as0 + c[1] * as1;
            float ed_a = c[0] * ad0 + c[1] * ad1;
            float es_b = c[2] * as0 + c[3] * as1;
            float ed_b = c[2] * ad0 + c[3] * ad1;
            es_a += __shfl_xor_sync(0xffffffffu, es_a, 1); es_a += __shfl_xor_sync(0xffffffffu, es_a, 2);
            ed_a += __shfl_xor_sync(0xffffffffu, ed_a, 1); ed_a += __shfl_xor_sync(0xffffffffu, ed_a, 2);
            es_b += __shfl_xor_sync(0xffffffffu, es_b, 1); es_b += __shfl_xor_sync(0xffffffffu, es_b, 2);
            ed_b += __shfl_xor_sync(0xffffffffu, ed_b, 1); ed_b += __shfl_xor_sync(0xffffffffu, ed_b, 2);
            if (tc == 0) {
                if (r0 < NN) { g_es1[(size_t)r0 * H1 + head] = es_a; g_ed1[(size_t)r0 * H1 + head] = ed_a; }
                if (r1 < NN) { g_es1[(size_t)r1 * H1 + head] = es_b; g_ed1[(size_t)r1 * H1 + head] = ed_b; }
            }
        }
    }
}

// ---------------- layer-1 aggregation: warp per dst, online softmax, ELU ----------------
__global__ __launch_bounds__(256) void agg1_kernel() {
    int warp = (blockIdx.x * blockDim.x + threadIdx.x) >> 5;
    int lane = threadIdx.x & 31;
    if (warp >= NN) return;
    int dst = warp;
    int head0 = lane >> 3;
    float edv = (lane < 8) ? g_ed1[(size_t)dst * H1 + lane] : 0.f;
    float m = -INFINITY, s = 0.f;
    float acc0 = 0.f, acc1 = 0.f;
    int beg = g_rowptr[dst], end = g_rowptr[dst + 1];
    for (int e = beg; e < end; e++) {
        int src = g_col[e];
        float scale = 1.f, w = 0.f;
        if (lane < 8) {
            float ev = g_es1[(size_t)src * H1 + lane] + edv;
            ev = ev > 0.f ? ev : 0.2f * ev;
            float nm = fmaxf(m, ev);
            scale = __expf(m - nm);
            w = __expf(ev - nm);
            m = nm;
            s = s * scale + w;
        }
        float sc0 = __shfl_sync(0xffffffffu, scale, head0);
        float w0  = __shfl_sync(0xffffffffu, w,     head0);
        float sc1 = __shfl_sync(0xffffffffu, scale, head0 + 4);
        float w1  = __shfl_sync(0xffffffffu, w,     head0 + 4);
        float hv0 = g_h1[(size_t)src * HD + lane];
        float hv1 = g_h1[(size_t)src * HD + lane + 32];
        acc0 = acc0 * sc0 + hv0 * w0;
        acc1 = acc1 * sc1 + hv1 * w1;
    }
    float s0 = __shfl_sync(0xffffffffu, s, head0);
    float s1 = __shfl_sync(0xffffffffu, s, head0 + 4);
    float o0 = acc0 / s0;
    float o1 = acc1 / s1;
    o0 = o0 > 0.f ? o0 : expm1f(o0);
    o1 = o1 > 0.f ? o1 : expm1f(o1);
    g_h1act[(size_t)dst * HD + lane] = o0;
    g_h1act[(size_t)dst * HD + lane + 32] = o1;
}

// ---------------- GEMM2 + fused es2/ed2 ----------------
__global__ __launch_bounds__(256) void gemm2_kernel(const float* __restrict__ W2,
                                                    const float* __restrict__ a2s,
                                                    const float* __restrict__ a2d) {
    __shared__ float Ws[HD * CC];
    int t = threadIdx.x;
    {
        float4 v = ((const float4*)W2)[t];
        ((float4*)Ws)[t] = v;
    }
    __syncthreads();
    int idx = blockIdx.x * 256 + t;
    if (idx >= NN * CC) return;
    int n = idx >> 4, c = idx & 15;
    const float4* h4 = (const float4*)(g_h1act + (size_t)n * HD);
    float sum = 0.f;
    #pragma unroll
    for (int j = 0; j < 16; j++) {
        float4 v = h4[j];
        sum += v.x * Ws[(4 * j + 0) * CC + c];
        sum += v.y * Ws[(4 * j + 1) * CC + c];
        sum += v.z * Ws[(4 * j + 2) * CC + c];
        sum += v.w * Ws[(4 * j + 3) * CC + c];
    }
    g_h2[idx] = sum;
    float es = sum * a2s[c];
    float ed = sum * a2d[c];
    #pragma unroll
    for (int off = 1; off < 16; off <<= 1) {
        es += __shfl_xor_sync(0xffffffffu, es, off, 16);
        ed += __shfl_xor_sync(0xffffffffu, ed, off, 16);
    }
    if (c == 0) { g_es2[n] = es; g_ed2[n] = ed; }
}

// ---------------- layer-2 aggregation + log_softmax : half-warp per dst ----------------
__global__ __launch_bounds__(256) void agg2_kernel(float* __restrict__ out) {
    int gw = (blockIdx.x * blockDim.x + threadIdx.x) >> 5;
    int lane = threadIdx.x & 31;
    int half = lane >> 4;
    int r = lane & 15;
    int dst = gw * 2 + half;
    float edv = g_ed2[dst];
    float m = -INFINITY, s = 0.f, acc = 0.f;
    int beg = g_rowptr[dst], end = g_rowptr[dst + 1];
    for (int e = beg; e < end; e++) {
        int src = g_col[e];
        float ev = g_es2[src] + edv;
        ev = ev > 0.f ? ev : 0.2f * ev;
        float nm = fmaxf(m, ev);
        float scale = __expf(m - nm);
        float w = __expf(ev - nm);
        m = nm;
        s = s * scale + w;
        acc = acc * scale + g_h2[(size_t)src * CC + r] * w;
    }
    float o = acc / s;
    float mx = o;
    #pragma unroll
    for (int off = 8; off; off >>= 1)
        mx = fmaxf(mx, __shfl_xor_sync(0xffffffffu, mx, off, 16));
    float se = __expf(o - mx);
    #pragma unroll
    for (int off = 8; off; off >>= 1)
        se += __shfl_xor_sync(0xffffffffu, se, off, 16);
    out[(size_t)dst * CC + r] = o - mx - logf(se);
}

// ---------------- launch ----------------
extern "C" void kernel_launch(void* const* d_in, const int* in_sizes, int n_in,
                              void* d_out, int out_size) {
    const float* x    = (const float*)d_in[0];
    const void*  ei   = d_in[1];
    const float* W1   = (const float*)d_in[2];
    const float* a1s  = (const float*)d_in[3];
    const float* a1d  = (const float*)d_in[4];
    const float* W2   = (const float*)d_in[5];
    const float* a2s  = (const float*)d_in[6];
    const float* a2d  = (const float*)d_in[7];
    float* out = (float*)d_out;

    cudaFuncSetAttribute(gemm1_mma_kernel, cudaFuncAttributeMaxDynamicSharedMemorySize, G1_SMEM);

    init_kernel<<<NB, 256>>>((const int*)ei, W1);
    convert_hist_kernel<<<(ET + 255) / 256, 256>>>(ei);
    scan_partial_kernel<<<NB, 256>>>();
    scan_blocks_kernel<<<1, 512>>>();
    scan_apply_kernel<<<NB, 256>>>();
    scatter_kernel<<<(ET + 255) / 256, 256>>>();

    gemm1_mma_kernel<<<(NN + 127) / 128, 256, G1_SMEM>>>(x, a1s, a1d);
    agg1_kernel<<<(NN * 32 + 255) / 256, 256>>>();

    gemm2_kernel<<<(NN * CC + 255) / 256, 256>>>(W2, a2s, a2d);
    agg2_kernel<<<(NN * 16 + 255) / 256, 256>>>(out);
}

// round 8
// speedup vs baseline: 1.6345x; 1.6345x over previous
#include <cuda_runtime.h>
#include <cuda_bf16.h>
#include <math.h>
#include <stdint.h>

#define NN   100000
#define EE   1600000
#define ET   1700000      // EE + NN self loops
#define FIN  512
#define HD   64           // H1*D1
#define H1   8
#define D1   8
#define CC   16
#define NB   ((NN + 255) / 256)   // 391 scan blocks

// ---------------- scratch (static device memory; no allocations) ----------------
__device__ int   g_flag;
__device__ int   g_src[ET];
__device__ int   g_dst[ET];
__device__ int   g_col[ET];
__device__ int   g_counts[NN];
__device__ int   g_cursor[NN];
__device__ int   g_rowptr[NN + 1];
__device__ int   g_bsum[NB];
__device__ int   g_boff[NB];
__device__ float g_h1[(size_t)NN * HD];
__device__ float g_h1act[(size_t)NN * HD];
__device__ float g_es1[(size_t)NN * H1];
__device__ float g_ed1[(size_t)NN * H1];
__device__ float g_h2[(size_t)NN * CC];
__device__ float g_es2[NN];
__device__ float g_ed2[NN];

// ---------------- init: zero counts + parallel dtype detection ----------------
__global__ __launch_bounds__(256) void init_kernel(const int* ei32) {
    int i = blockIdx.x * blockDim.x + threadIdx.x;
    if (i < NN) g_counts[i] = 0;
    if (blockIdx.x == 0 && threadIdx.x < 32) {
        int lane = threadIdx.x;
        int bad = 0;
        for (int j = lane; j < 256; j += 32) {
            int k = j * 6250;
            if (ei32[2 * k + 1] != 0) bad = 1;
        }
        unsigned b = __ballot_sync(0xffffffffu, bad);
        if (lane == 0) g_flag = (b == 0) ? 1 : 0;
    }
}

// ---------------- convert + histogram in one edge pass ----------------
__global__ __launch_bounds__(256) void convert_hist_kernel(const void* ei) {
    int e = blockIdx.x * blockDim.x + threadIdx.x;
    if (e >= ET) return;
    int s, d;
    if (e < EE) {
        if (g_flag) {
            const long long* p = (const long long*)ei;
            s = (int)p[e]; d = (int)p[EE + e];
        } else {
            const int* p = (const int*)ei;
            s = p[e]; d = p[EE + e];
        }
    } else {
        s = e - EE; d = e - EE;
    }
    g_src[e] = s; g_dst[e] = d;
    atomicAdd(&g_counts[d], 1);
}

// ---------------- parallel scan ----------------
__global__ __launch_bounds__(256) void scan_partial_kernel() {
    __shared__ int wsum[8];
    int t = threadIdx.x;
    int i = blockIdx.x * 256 + t;
    int c = (i < NN) ? g_counts[i] : 0;
    int v = c;
    #pragma unroll
    for (int off = 1; off < 32; off <<= 1) v += __shfl_xor_sync(0xffffffffu, v, off);
    if ((t & 31) == 0) wsum[t >> 5] = v;
    __syncthreads();
    if (t == 0) {
        int s = 0;
        #pragma unroll
        for (int w = 0; w < 8; w++) s += wsum[w];
        g_bsum[blockIdx.x] = s;
    }
}

__global__ __launch_bounds__(512) void scan_blocks_kernel() {
    __shared__ int sh[512];
    int t = threadIdx.x;
    sh[t] = (t < NB) ? g_bsum[t] : 0;
    __syncthreads();
    for (int off = 1; off < 512; off <<= 1) {
        int v = (t >= off) ? sh[t - off] : 0;
        __syncthreads();
        sh[t] += v;
        __syncthreads();
    }
    if (t < NB) g_boff[t] = (t == 0) ? 0 : sh[t - 1];
}

__global__ __launch_bounds__(256) void scan_apply_kernel() {
    __shared__ int woff[8];
    int t = threadIdx.x, lane = t & 31, wid = t >> 5;
    int i = blockIdx.x * 256 + t;
    int c = (i < NN) ? g_counts[i] : 0;
    int incl = c;
    #pragma unroll
    for (int off = 1; off < 32; off <<= 1) {
        int v = __shfl_up_sync(0xffffffffu, incl, off);
        if (lane >= off) incl += v;
    }
    if (lane == 31) woff[wid] = incl;
    __syncthreads();
    if (t == 0) {
        int run = 0;
        #pragma unroll
        for (int w = 0; w < 8; w++) { int v = woff[w]; woff[w] = run; run += v; }
    }
    __syncthreads();
    int excl = incl - c + woff[wid] + g_boff[blockIdx.x];
    if (i < NN) { g_rowptr[i] = excl; g_cursor[i] = excl; }
    if (i == NN - 1) g_rowptr[NN] = ET;
}

__global__ __launch_bounds__(256) void scatter_kernel() {
    int e = blockIdx.x * blockDim.x + threadIdx.x;
    if (e < ET) {
        int d = g_dst[e];
        int pos = atomicAdd(&g_cursor[d], 1);
        g_col[pos] = g_src[e];
    }
}

// ---------------- GEMM1 via mma.sync split-bf16 + fused es/ed (R5 design) ----------------
#define KC 256
#define ST 264
#define G1_SMEM (2 * 64 * ST * 2)

__device__ __forceinline__ void cvt_pair(float vx, float vy, uint32_t& hi, uint32_t& lo) {
    asm("cvt.rn.bf16x2.f32 %0, %1, %2;" : "=r"(hi) : "f"(vy), "f"(vx));
    float h0 = __uint_as_float(hi << 16);
    float h1 = __uint_as_float(hi & 0xFFFF0000u);
    float r0 = vx - h0, r1 = vy - h1;
    asm("cvt.rn.bf16x2.f32 %0, %1, %2;" : "=r"(lo) : "f"(r1), "f"(r0));
}

__device__ __forceinline__ void mma16816(float* c, const uint32_t* a, uint32_t b0, uint32_t b1) {
    asm volatile(
        "mma.sync.aligned.m16n8k16.row.col.f32.bf16.bf16.f32 "
        "{%0,%1,%2,%3}, {%4,%5,%6,%7}, {%8,%9}, {%0,%1,%2,%3};"
        : "+f"(c[0]), "+f"(c[1]), "+f"(c[2]), "+f"(c[3])
        : "r"(a[0]), "r"(a[1]), "r"(a[2]), "r"(a[3]), "r"(b0), "r"(b1));
}

__global__ __launch_bounds__(256, 2) void gemm1_mma_kernel(const float* __restrict__ x,
                                                           const float* __restrict__ W,
                                                           const float* __restrict__ a1s,
                                                           const float* __restrict__ a1d) {
    extern __shared__ __nv_bfloat16 ws[];
    __nv_bfloat16* whi = ws;
    __nv_bfloat16* wlo = ws + 64 * ST;
    int tid = threadIdx.x;
    int wid = tid >> 5, lane = tid & 31;
    int g = lane >> 2, tc = lane & 3;
    int wm = wid & 3, wn = wid >> 2;
    int row_base = blockIdx.x * 128 + wm * 32;

    float acc[2][4][4];
    #pragma unroll
    for (int mt = 0; mt < 2; mt++)
        #pragma unroll
        for (int nt = 0; nt < 4; nt++)
            #pragma unroll
            for (int q = 0; q < 4; q++) acc[mt][nt][q] = 0.f;

    for (int ch = 0; ch < 2; ch++) {
        int kb = ch * KC;
        for (int i = tid; i < 64 * KC; i += 256) {
            int kk = i >> 6;
            int n = i & 63;
            float v = W[(size_t)(kb + kk) * HD + n];
            __nv_bfloat16 h = __float2bfloat16_rn(v);
            float r = v - __bfloat162float(h);
            whi[n * ST + kk] = h;
            wlo[n * ST + kk] = __float2bfloat16_rn(r);
        }
        __syncthreads();

        for (int ks = 0; ks < KC / 16; ks++) {
            int k0 = kb + ks * 16;
            uint32_t ah[2][4], al[2][4];
            #pragma unroll
            for (int mt = 0; mt < 2; mt++) {
                int r0 = row_base + mt * 16 + g;
                int r1 = r0 + 8;
                const float* p0 = x + (size_t)r0 * FIN + k0 + tc * 2;
                const float* p1 = x + (size_t)r1 * FIN + k0 + tc * 2;
                float2 z = make_float2(0.f, 0.f);
                float2 v0 = (r0 < NN) ? *(const float2*)p0 : z;
                float2 v1 = (r1 < NN) ? *(const float2*)p1 : z;
                float2 v2 = (r0 < NN) ? *(const float2*)(p0 + 8) : z;
                float2 v3 = (r1 < NN) ? *(const float2*)(p1 + 8) : z;
                cvt_pair(v0.x, v0.y, ah[mt][0], al[mt][0]);
                cvt_pair(v1.x, v1.y, ah[mt][1], al[mt][1]);
                cvt_pair(v2.x, v2.y, ah[mt][2], al[mt][2]);
                cvt_pair(v3.x, v3.y, ah[mt][3], al[mt][3]);
            }
            int kl = ks * 16 + tc * 2;
            #pragma unroll
            for (int nt = 0; nt < 4; nt++) {
                int n = wn * 32 + nt * 8 + g;
                const __nv_bfloat16* ph = whi + n * ST + kl;
                const __nv_bfloat16* pl = wlo + n * ST + kl;
                uint32_t bh0 = *(const uint32_t*)ph;
                uint32_t bh1 = *(const uint32_t*)(ph + 8);
                uint32_t bl0 = *(const uint32_t*)pl;
                uint32_t bl1 = *(const uint32_t*)(pl + 8);
                #pragma unroll
                for (int mt = 0; mt < 2; mt++) {
                    mma16816(acc[mt][nt], ah[mt], bh0, bh1);
                    mma16816(acc[mt][nt], al[mt], bh0, bh1);
                    mma16816(acc[mt][nt], ah[mt], bl0, bl1);
                }
            }
        }
        __syncthreads();
    }

    int col_base = wn * 32;
    #pragma unroll
    for (int mt = 0; mt < 2; mt++) {
        int r0 = row_base + mt * 16 + g;
        int r1 = r0 + 8;
        #pragma unroll
        for (int nt = 0; nt < 4; nt++) {
            int col = col_base + nt * 8 + tc * 2;
            float* c = acc[mt][nt];
            if (r0 < NN) *(float2*)(g_h1 + (size_t)r0 * HD + col) = make_float2(c[0], c[1]);
            if (r1 < NN) *(float2*)(g_h1 + (size_t)r1 * HD + col) = make_float2(c[2], c[3]);
            int head = (col_base >> 3) + nt;
            float as0 = a1s[head * 8 + tc * 2], as1 = a1s[head * 8 + tc * 2 + 1];
            float ad0 = a1d[head * 8 + tc * 2], ad1 = a1d[head * 8 + tc * 2 + 1];
            float es_a = c[0] * as0 + c[1] * as1;
            float ed_a = c[0] * ad0 + c[1] * ad1;
            float es_b = c[2] * as0 + c[3] * as1;
            float ed_b = c[2] * ad0 + c[3] * ad1;
            es_a += __shfl_xor_sync(0xffffffffu, es_a, 1); es_a += __shfl_xor_sync(0xffffffffu, es_a, 2);
            ed_a += __shfl_xor_sync(0xffffffffu, ed_a, 1); ed_a += __shfl_xor_sync(0xffffffffu, ed_a, 2);
            es_b += __shfl_xor_sync(0xffffffffu, es_b, 1); es_b += __shfl_xor_sync(0xffffffffu, es_b, 2);
            ed_b += __shfl_xor_sync(0xffffffffu, ed_b, 1); ed_b += __shfl_xor_sync(0xffffffffu, ed_b, 2);
            if (tc == 0) {
                if (r0 < NN) { g_es1[(size_t)r0 * H1 + head] = es_a; g_ed1[(size_t)r0 * H1 + head] = ed_a; }
                if (r1 < NN) { g_es1[(size_t)r1 * H1 + head] = es_b; g_ed1[(size_t)r1 * H1 + head] = ed_b; }
            }
        }
    }
}

// ---------------- layer-1 aggregation: warp per dst, online softmax, ELU ----------------
__global__ __launch_bounds__(256) void agg1_kernel() {
    int warp = (blockIdx.x * blockDim.x + threadIdx.x) >> 5;
    int lane = threadIdx.x & 31;
    if (warp >= NN) return;
    int dst = warp;
    int head0 = lane >> 3;
    float edv = (lane < 8) ? g_ed1[(size_t)dst * H1 + lane] : 0.f;
    float m = -INFINITY, s = 0.f;
    float acc0 = 0.f, acc1 = 0.f;
    int beg = g_rowptr[dst], end = g_rowptr[dst + 1];
    for (int e = beg; e < end; e++) {
        int src = g_col[e];
        float scale = 1.f, w = 0.f;
        if (lane < 8) {
            float ev = g_es1[(size_t)src * H1 + lane] + edv;
            ev = ev > 0.f ? ev : 0.2f * ev;
            float nm = fmaxf(m, ev);
            scale = __expf(m - nm);
            w = __expf(ev - nm);
            m = nm;
            s = s * scale + w;
        }
        float sc0 = __shfl_sync(0xffffffffu, scale, head0);
        float w0  = __shfl_sync(0xffffffffu, w,     head0);
        float sc1 = __shfl_sync(0xffffffffu, scale, head0 + 4);
        float w1  = __shfl_sync(0xffffffffu, w,     head0 + 4);
        float hv0 = g_h1[(size_t)src * HD + lane];
        float hv1 = g_h1[(size_t)src * HD + lane + 32];
        acc0 = acc0 * sc0 + hv0 * w0;
        acc1 = acc1 * sc1 + hv1 * w1;
    }
    float s0 = __shfl_sync(0xffffffffu, s, head0);
    float s1 = __shfl_sync(0xffffffffu, s, head0 + 4);
    float o0 = acc0 / s0;
    float o1 = acc1 / s1;
    o0 = o0 > 0.f ? o0 : expm1f(o0);
    o1 = o1 > 0.f ? o1 : expm1f(o1);
    g_h1act[(size_t)dst * HD + lane] = o0;
    g_h1act[(size_t)dst * HD + lane + 32] = o1;
}

// ---------------- GEMM2 + fused es2/ed2 ----------------
__global__ __launch_bounds__(256) void gemm2_kernel(const float* __restrict__ W2,
                                                    const float* __restrict__ a2s,
                                                    const float* __restrict__ a2d) {
    __shared__ float Ws[HD * CC];
    int t = threadIdx.x;
    {
        float4 v = ((const float4*)W2)[t];
        ((float4*)Ws)[t] = v;
    }
    __syncthreads();
    int idx = blockIdx.x * 256 + t;
    if (idx >= NN * CC) return;
    int n = idx >> 4, c = idx & 15;
    const float4* h4 = (const float4*)(g_h1act + (size_t)n * HD);
    float sum = 0.f;
    #pragma unroll
    for (int j = 0; j < 16; j++) {
        float4 v = h4[j];
        sum += v.x * Ws[(4 * j + 0) * CC + c];
        sum += v.y * Ws[(4 * j + 1) * CC + c];
        sum += v.z * Ws[(4 * j + 2) * CC + c];
        sum += v.w * Ws[(4 * j + 3) * CC + c];
    }
    g_h2[idx] = sum;
    float es = sum * a2s[c];
    float ed = sum * a2d[c];
    #pragma unroll
    for (int off = 1; off < 16; off <<= 1) {
        es += __shfl_xor_sync(0xffffffffu, es, off, 16);
        ed += __shfl_xor_sync(0xffffffffu, ed, off, 16);
    }
    if (c == 0) { g_es2[n] = es; g_ed2[n] = ed; }
}

// ---------------- layer-2 aggregation + log_softmax : half-warp per dst ----------------
__global__ __launch_bounds__(256) void agg2_kernel(float* __restrict__ out) {
    int gw = (blockIdx.x * blockDim.x + threadIdx.x) >> 5;
    int lane = threadIdx.x & 31;
    int half = lane >> 4;
    int r = lane & 15;
    int dst = gw * 2 + half;
    float edv = g_ed2[dst];
    float m = -INFINITY, s = 0.f, acc = 0.f;
    int beg = g_rowptr[dst], end = g_rowptr[dst + 1];
    for (int e = beg; e < end; e++) {
        int src = g_col[e];
        float ev = g_es2[src] + edv;
        ev = ev > 0.f ? ev : 0.2f * ev;
        float nm = fmaxf(m, ev);
        float scale = __expf(m - nm);
        float w = __expf(ev - nm);
        m = nm;
        s = s * scale + w;
        acc = acc * scale + g_h2[(size_t)src * CC + r] * w;
    }
    float o = acc / s;
    float mx = o;
    #pragma unroll
    for (int off = 8; off; off >>= 1)
        mx = fmaxf(mx, __shfl_xor_sync(0xffffffffu, mx, off, 16));
    float se = __expf(o - mx);
    #pragma unroll
    for (int off = 8; off; off >>= 1)
        se += __shfl_xor_sync(0xffffffffu, se, off, 16);
    out[(size_t)dst * CC + r] = o - mx - logf(se);
}

// ---------------- launch ----------------
extern "C" void kernel_launch(void* const* d_in, const int* in_sizes, int n_in,
                              void* d_out, int out_size) {
    const float* x    = (const float*)d_in[0];
    const void*  ei   = d_in[1];
    const float* W1   = (const float*)d_in[2];
    const float* a1s  = (const float*)d_in[3];
    const float* a1d  = (const float*)d_in[4];
    const float* W2   = (const float*)d_in[5];
    const float* a2s  = (const float*)d_in[6];
    const float* a2d  = (const float*)d_in[7];
    float* out = (float*)d_out;

    cudaFuncSetAttribute(gemm1_mma_kernel, cudaFuncAttributeMaxDynamicSharedMemorySize, G1_SMEM);

    // NOTE: launch order arranged so gemm1 is launch #4 (the one ncu captures).
    init_kernel<<<NB, 256>>>((const int*)ei);
    convert_hist_kernel<<<(ET + 255) / 256, 256>>>(ei);
    scan_partial_kernel<<<NB, 256>>>();
    gemm1_mma_kernel<<<(NN + 127) / 128, 256, G1_SMEM>>>(x, W1, a1s, a1d);   // launch #4
    scan_blocks_kernel<<<1, 512>>>();
    scan_apply_kernel<<<NB, 256>>>();
    scatter_kernel<<<(ET + 255) / 256, 256>>>();
    agg1_kernel<<<(NN * 32 + 255) / 256, 256>>>();

    gemm2_kernel<<<(NN * CC + 255) / 256, 256>>>(W2, a2s, a2d);
    agg2_kernel<<<(NN * 16 + 255) / 256, 256>>>(out);
}

// round 9
// speedup vs baseline: 1.6793x; 1.0274x over previous
#include <cuda_runtime.h>
#include <cuda_bf16.h>
#include <math.h>
#include <stdint.h>

#define NN   100000
#define EE   1600000
#define ET   1700000      // EE + NN self loops
#define FIN  512
#define HD   64           // H1*D1
#define H1   8
#define D1   8
#define CC   16
#define NB   ((NN + 255) / 256)   // 391 scan blocks

// ---------------- scratch (static device memory; no allocations) ----------------
__device__ int   g_flag;
__device__ int   g_src[ET];
__device__ int   g_dst[ET];
__device__ int   g_col[ET];
__device__ int   g_counts[NN];
__device__ int   g_cursor[NN];
__device__ int   g_rowptr[NN + 1];
__device__ int   g_bsum[NB];
__device__ int   g_boff[NB];
__device__ __nv_bfloat16 g_wbhi[HD * FIN];   // W1^T bf16 hi, [n][k]
__device__ __nv_bfloat16 g_wblo[HD * FIN];   // W1^T bf16 lo, [n][k]
__device__ float g_h1[(size_t)NN * HD];
__device__ float g_h1act[(size_t)NN * HD];
__device__ float g_es1[(size_t)NN * H1];
__device__ float g_ed1[(size_t)NN * H1];
__device__ float g_h2[(size_t)NN * CC];
__device__ float g_es2[NN];
__device__ float g_ed2[NN];

// ---------------- init: zero counts + dtype detect + W1 hi/lo convert ----------------
__global__ __launch_bounds__(256) void init_kernel(const int* ei32, const float* __restrict__ W1) {
    int i = blockIdx.x * blockDim.x + threadIdx.x;
    if (i < NN) g_counts[i] = 0;
    if (i < HD * FIN) {                     // out [n][k] = W1[k][n]
        int n = i >> 9, k = i & 511;
        float v = W1[(size_t)k * HD + n];
        __nv_bfloat16 h = __float2bfloat16_rn(v);
        g_wbhi[i] = h;
        g_wblo[i] = __float2bfloat16_rn(v - __bfloat162float(h));
    }
    if (blockIdx.x == 0 && threadIdx.x < 32) {
        int lane = threadIdx.x;
        int bad = 0;
        for (int j = lane; j < 256; j += 32) {
            int k = j * 6250;
            if (ei32[2 * k + 1] != 0) bad = 1;
        }
        unsigned b = __ballot_sync(0xffffffffu, bad);
        if (lane == 0) g_flag = (b == 0) ? 1 : 0;
    }
}

// ---------------- convert + histogram in one edge pass ----------------
__global__ __launch_bounds__(256) void convert_hist_kernel(const void* ei) {
    int e = blockIdx.x * blockDim.x + threadIdx.x;
    if (e >= ET) return;
    int s, d;
    if (e < EE) {
        if (g_flag) {
            const long long* p = (const long long*)ei;
            s = (int)p[e]; d = (int)p[EE + e];
        } else {
            const int* p = (const int*)ei;
            s = p[e]; d = p[EE + e];
        }
    } else {
        s = e - EE; d = e - EE;
    }
    g_src[e] = s; g_dst[e] = d;
    atomicAdd(&g_counts[d], 1);
}

// ---------------- parallel scan ----------------
__global__ __launch_bounds__(256) void scan_partial_kernel() {
    __shared__ int wsum[8];
    int t = threadIdx.x;
    int i = blockIdx.x * 256 + t;
    int c = (i < NN) ? g_counts[i] : 0;
    int v = c;
    #pragma unroll
    for (int off = 1; off < 32; off <<= 1) v += __shfl_xor_sync(0xffffffffu, v, off);
    if ((t & 31) == 0) wsum[t >> 5] = v;
    __syncthreads();
    if (t == 0) {
        int s = 0;
        #pragma unroll
        for (int w = 0; w < 8; w++) s += wsum[w];
        g_bsum[blockIdx.x] = s;
    }
}

__global__ __launch_bounds__(512) void scan_blocks_kernel() {
    __shared__ int sh[512];
    int t = threadIdx.x;
    sh[t] = (t < NB) ? g_bsum[t] : 0;
    __syncthreads();
    for (int off = 1; off < 512; off <<= 1) {
        int v = (t >= off) ? sh[t - off] : 0;
        __syncthreads();
        sh[t] += v;
        __syncthreads();
    }
    if (t < NB) g_boff[t] = (t == 0) ? 0 : sh[t - 1];
}

__global__ __launch_bounds__(256) void scan_apply_kernel() {
    __shared__ int woff[8];
    int t = threadIdx.x, lane = t & 31, wid = t >> 5;
    int i = blockIdx.x * 256 + t;
    int c = (i < NN) ? g_counts[i] : 0;
    int incl = c;
    #pragma unroll
    for (int off = 1; off < 32; off <<= 1) {
        int v = __shfl_up_sync(0xffffffffu, incl, off);
        if (lane >= off) incl += v;
    }
    if (lane == 31) woff[wid] = incl;
    __syncthreads();
    if (t == 0) {
        int run = 0;
        #pragma unroll
        for (int w = 0; w < 8; w++) { int v = woff[w]; woff[w] = run; run += v; }
    }
    __syncthreads();
    int excl = incl - c + woff[wid] + g_boff[blockIdx.x];
    if (i < NN) { g_rowptr[i] = excl; g_cursor[i] = excl; }
    if (i == NN - 1) g_rowptr[NN] = ET;
}

__global__ __launch_bounds__(256) void scatter_kernel() {
    int e = blockIdx.x * blockDim.x + threadIdx.x;
    if (e < ET) {
        int d = g_dst[e];
        int pos = atomicAdd(&g_cursor[d], 1);
        g_col[pos] = g_src[e];
    }
}

// ---------------- GEMM1: cp.async-staged A + HMMA split-bf16 + fused es/ed ----------------
#define BKG   32                  // K per stage
#define NSTG  4                   // stages
#define ASTR  36                  // fp32 stride per A row
#define STAGE_B (128 * ASTR * 4)  // 18432 bytes
#define G1_SMEM (NSTG * STAGE_B)  // 73728 bytes

__device__ __forceinline__ void cp_async_cg(uint32_t saddr, const void* gptr, int srcsz) {
    asm volatile("cp.async.cg.shared.global [%0], [%1], 16, %2;"
                 :: "r"(saddr), "l"(gptr), "r"(srcsz));
}
__device__ __forceinline__ void cp_commit() { asm volatile("cp.async.commit_group;"); }

__device__ __forceinline__ void cvt_pair(float vx, float vy, uint32_t& hi, uint32_t& lo) {
    asm("cvt.rn.bf16x2.f32 %0, %1, %2;" : "=r"(hi) : "f"(vy), "f"(vx));
    float h0 = __uint_as_float(hi << 16);
    float h1 = __uint_as_float(hi & 0xFFFF0000u);
    float r0 = vx - h0, r1 = vy - h1;
    asm("cvt.rn.bf16x2.f32 %0, %1, %2;" : "=r"(lo) : "f"(r1), "f"(r0));
}

__device__ __forceinline__ void mma16816(float* c, const uint32_t* a, uint32_t b0, uint32_t b1) {
    asm volatile(
        "mma.sync.aligned.m16n8k16.row.col.f32.bf16.bf16.f32 "
        "{%0,%1,%2,%3}, {%4,%5,%6,%7}, {%8,%9}, {%0,%1,%2,%3};"
        : "+f"(c[0]), "+f"(c[1]), "+f"(c[2]), "+f"(c[3])
        : "r"(a[0]), "r"(a[1]), "r"(a[2]), "r"(a[3]), "r"(b0), "r"(b1));
}

__global__ __launch_bounds__(256, 2) void gemm1_mma_kernel(const float* __restrict__ x,
                                                           const float* __restrict__ a1s,
                                                           const float* __restrict__ a1d) {
    extern __shared__ float sA[];           // [NSTG][128][ASTR]
    uint32_t sbase;
    asm("{ .reg .u64 t; cvta.to.shared.u64 t, %1; cvt.u32.u64 %0, t; }" : "=r"(sbase) : "l"(sA));

    int tid = threadIdx.x;
    int wid = tid >> 5, lane = tid & 31;
    int g = lane >> 2, tc = lane & 3;
    int wm = wid & 3, wn = wid >> 2;
    int block_row = blockIdx.x * 128;
    int row_base = block_row + wm * 32;

    // A loader mapping: 1024 float4 per stage; thread covers 4 (idx = tid + 256*i)
    // row = idx>>3 (8 float4 per 32-float row), c4 = idx&7
    float acc[2][4][4];
    #pragma unroll
    for (int mt = 0; mt < 2; mt++)
        #pragma unroll
        for (int nt = 0; nt < 4; nt++)
            #pragma unroll
            for (int q = 0; q < 4; q++) acc[mt][nt][q] = 0.f;

    const int NSTEP = FIN / BKG;            // 16

    #pragma unroll
    for (int s = 0; s < NSTG - 1; s++) {    // prologue: 3 stages
        #pragma unroll
        for (int i = 0; i < 4; i++) {
            int idx = tid + 256 * i;
            int row = idx >> 3, c4 = idx & 7;
            int grow = block_row + row;
            uint32_t sa = sbase + (uint32_t)s * STAGE_B + (row * ASTR + c4 * 4) * 4;
            cp_async_cg(sa, x + (size_t)grow * FIN + s * BKG + c4 * 4,
                        (grow < NN) ? 16 : 0);
        }
        cp_commit();
    }

    for (int step = 0; step < NSTEP; step++) {
        int rem = NSTEP - 1 - step;
        if (rem >= 3) { asm volatile("cp.async.wait_group 2;"); }
        else if (rem == 2) { asm volatile("cp.async.wait_group 2;"); }
        else if (rem == 1) { asm volatile("cp.async.wait_group 1;"); }
        else { asm volatile("cp.async.wait_group 0;"); }
        __syncthreads();

        // issue next stage (overwrites buffer read at step-1; safe after sync)
        int nxt = step + NSTG - 1;
        if (nxt < NSTEP) {
            int sbuf = nxt & (NSTG - 1);
            #pragma unroll
            for (int i = 0; i < 4; i++) {
                int idx = tid + 256 * i;
                int row = idx >> 3, c4 = idx & 7;
                int grow = block_row + row;
                uint32_t sa = sbase + (uint32_t)sbuf * STAGE_B + (row * ASTR + c4 * 4) * 4;
                cp_async_cg(sa, x + (size_t)grow * FIN + nxt * BKG + c4 * 4,
                            (grow < NN) ? 16 : 0);
            }
            cp_commit();
        }

        const float* sAc = sA + (step & (NSTG - 1)) * 128 * ASTR;
        #pragma unroll
        for (int ks = 0; ks < BKG / 16; ks++) {  // 2
            int kg = step * BKG + ks * 16;
            int kl = ks * 16 + tc * 2;
            uint32_t ah[2][4], al[2][4];
            #pragma unroll
            for (int mt = 0; mt < 2; mt++) {
                int lr0 = wm * 32 + mt * 16 + g;
                int lr1 = lr0 + 8;
                float2 v0 = *(const float2*)(sAc + lr0 * ASTR + kl);
                float2 v1 = *(const float2*)(sAc + lr1 * ASTR + kl);
                float2 v2 = *(const float2*)(sAc + lr0 * ASTR + kl + 8);
                float2 v3 = *(const float2*)(sAc + lr1 * ASTR + kl + 8);
                cvt_pair(v0.x, v0.y, ah[mt][0], al[mt][0]);
                cvt_pair(v1.x, v1.y, ah[mt][1], al[mt][1]);
                cvt_pair(v2.x, v2.y, ah[mt][2], al[mt][2]);
                cvt_pair(v3.x, v3.y, ah[mt][3], al[mt][3]);
            }
            #pragma unroll
            for (int nt = 0; nt < 4; nt++) {
                int n = wn * 32 + nt * 8 + g;
                const __nv_bfloat16* ph = g_wbhi + (size_t)n * FIN + kg + tc * 2;
                const __nv_bfloat16* pl = g_wblo + (size_t)n * FIN + kg + tc * 2;
                uint32_t bh0 = *(const uint32_t*)ph;
                uint32_t bh1 = *(const uint32_t*)(ph + 8);
                uint32_t bl0 = *(const uint32_t*)pl;
                uint32_t bl1 = *(const uint32_t*)(pl + 8);
                #pragma unroll
                for (int mt = 0; mt < 2; mt++) {
                    mma16816(acc[mt][nt], ah[mt], bh0, bh1);
                    mma16816(acc[mt][nt], al[mt], bh0, bh1);
                    mma16816(acc[mt][nt], ah[mt], bl0, bl1);
                }
            }
        }
    }

    // ---- epilogue: write h1, fused es/ed ----
    int col_base = wn * 32;
    #pragma unroll
    for (int mt = 0; mt < 2; mt++) {
        int r0 = row_base + mt * 16 + g;
        int r1 = r0 + 8;
        #pragma unroll
        for (int nt = 0; nt < 4; nt++) {
            int col = col_base + nt * 8 + tc * 2;
            float* c = acc[mt][nt];
            if (r0 < NN) *(float2*)(g_h1 + (size_t)r0 * HD + col) = make_float2(c[0], c[1]);
            if (r1 < NN) *(float2*)(g_h1 + (size_t)r1 * HD + col) = make_float2(c[2], c[3]);
            int head = (col_base >> 3) + nt;
            float as0 = a1s[head * 8 + tc * 2], as1 = a1s[head * 8 + tc * 2 + 1];
            float ad0 = a1d[head * 8 + tc * 2], ad1 = a1d[head * 8 + tc * 2 + 1];
            float es_a = c[0] * as0 + c[1] * as1;
            float ed_a = c[0] * ad0 + c[1] * ad1;
            float es_b = c[2] * as0 + c[3] * as1;
            float ed_b = c[2] * ad0 + c[3] * ad1;
            es_a += __shfl_xor_sync(0xffffffffu, es_a, 1); es_a += __shfl_xor_sync(0xffffffffu, es_a, 2);
            ed_a += __shfl_xor_sync(0xffffffffu, ed_a, 1); ed_a += __shfl_xor_sync(0xffffffffu, ed_a, 2);
            es_b += __shfl_xor_sync(0xffffffffu, es_b, 1); es_b += __shfl_xor_sync(0xffffffffu, es_b, 2);
            ed_b += __shfl_xor_sync(0xffffffffu, ed_b, 1); ed_b += __shfl_xor_sync(0xffffffffu, ed_b, 2);
            if (tc == 0) {
                if (r0 < NN) { g_es1[(size_t)r0 * H1 + head] = es_a; g_ed1[(size_t)r0 * H1 + head] = ed_a; }
                if (r1 < NN) { g_es1[(size_t)r1 * H1 + head] = es_b; g_ed1[(size_t)r1 * H1 + head] = ed_b; }
            }
        }
    }
}

// ---------------- layer-1 aggregation: warp per dst, online softmax, ELU ----------------
__global__ __launch_bounds__(256) void agg1_kernel() {
    int warp = (blockIdx.x * blockDim.x + threadIdx.x) >> 5;
    int lane = threadIdx.x & 31;
    if (warp >= NN) return;
    int dst = warp;
    int head0 = lane >> 3;
    float edv = (lane < 8) ? g_ed1[(size_t)dst * H1 + lane] : 0.f;
    float m = -INFINITY, s = 0.f;
    float acc0 = 0.f, acc1 = 0.f;
    int beg = g_rowptr[dst], end = g_rowptr[dst + 1];
    for (int e = beg; e < end; e++) {
        int src = g_col[e];
        float scale = 1.f, w = 0.f;
        if (lane < 8) {
            float ev = g_es1[(size_t)src * H1 + lane] + edv;
            ev = ev > 0.f ? ev : 0.2f * ev;
            float nm = fmaxf(m, ev);
            scale = __expf(m - nm);
            w = __expf(ev - nm);
            m = nm;
            s = s * scale + w;
        }
        float sc0 = __shfl_sync(0xffffffffu, scale, head0);
        float w0  = __shfl_sync(0xffffffffu, w,     head0);
        float sc1 = __shfl_sync(0xffffffffu, scale, head0 + 4);
        float w1  = __shfl_sync(0xffffffffu, w,     head0 + 4);
        float hv0 = g_h1[(size_t)src * HD + lane];
        float hv1 = g_h1[(size_t)src * HD + lane + 32];
        acc0 = acc0 * sc0 + hv0 * w0;
        acc1 = acc1 * sc1 + hv1 * w1;
    }
    float s0 = __shfl_sync(0xffffffffu, s, head0);
    float s1 = __shfl_sync(0xffffffffu, s, head0 + 4);
    float o0 = acc0 / s0;
    float o1 = acc1 / s1;
    o0 = o0 > 0.f ? o0 : expm1f(o0);
    o1 = o1 > 0.f ? o1 : expm1f(o1);
    g_h1act[(size_t)dst * HD + lane] = o0;
    g_h1act[(size_t)dst * HD + lane + 32] = o1;
}

// ---------------- GEMM2 + fused es2/ed2 ----------------
__global__ __launch_bounds__(256) void gemm2_kernel(const float* __restrict__ W2,
                                                    const float* __restrict__ a2s,
                                                    const float* __restrict__ a2d) {
    __shared__ float Ws[HD * CC];
    int t = threadIdx.x;
    {
        float4 v = ((const float4*)W2)[t];
        ((float4*)Ws)[t] = v;
    }
    __syncthreads();
    int idx = blockIdx.x * 256 + t;
    if (idx >= NN * CC) return;
    int n = idx >> 4, c = idx & 15;
    const float4* h4 = (const float4*)(g_h1act + (size_t)n * HD);
    float sum = 0.f;
    #pragma unroll
    for (int j = 0; j < 16; j++) {
        float4 v = h4[j];
        sum += v.x * Ws[(4 * j + 0) * CC + c];
        sum += v.y * Ws[(4 * j + 1) * CC + c];
        sum += v.z * Ws[(4 * j + 2) * CC + c];
        sum += v.w * Ws[(4 * j + 3) * CC + c];
    }
    g_h2[idx] = sum;
    float es = sum * a2s[c];
    float ed = sum * a2d[c];
    #pragma unroll
    for (int off = 1; off < 16; off <<= 1) {
        es += __shfl_xor_sync(0xffffffffu, es, off, 16);
        ed += __shfl_xor_sync(0xffffffffu, ed, off, 16);
    }
    if (c == 0) { g_es2[n] = es; g_ed2[n] = ed; }
}

// ---------------- layer-2 aggregation + log_softmax : half-warp per dst ----------------
__global__ __launch_bounds__(256) void agg2_kernel(float* __restrict__ out) {
    int gw = (blockIdx.x * blockDim.x + threadIdx.x) >> 5;
    int lane = threadIdx.x & 31;
    int half = lane >> 4;
    int r = lane & 15;
    int dst = gw * 2 + half;
    float edv = g_ed2[dst];
    float m = -INFINITY, s = 0.f, acc = 0.f;
    int beg = g_rowptr[dst], end = g_rowptr[dst + 1];
    for (int e = beg; e < end; e++) {
        int src = g_col[e];
        float ev = g_es2[src] + edv;
        ev = ev > 0.f ? ev : 0.2f * ev;
        float nm = fmaxf(m, ev);
        float scale = __expf(m - nm);
        float w = __expf(ev - nm);
        m = nm;
        s = s * scale + w;
        acc = acc * scale + g_h2[(size_t)src * CC + r] * w;
    }
    float o = acc / s;
    float mx = o;
    #pragma unroll
    for (int off = 8; off; off >>= 1)
        mx = fmaxf(mx, __shfl_xor_sync(0xffffffffu, mx, off, 16));
    float se = __expf(o - mx);
    #pragma unroll
    for (int off = 8; off; off >>= 1)
        se += __shfl_xor_sync(0xffffffffu, se, off, 16);
    out[(size_t)dst * CC + r] = o - mx - logf(se);
}

// ---------------- launch ----------------
extern "C" void kernel_launch(void* const* d_in, const int* in_sizes, int n_in,
                              void* d_out, int out_size) {
    const float* x    = (const float*)d_in[0];
    const void*  ei   = d_in[1];
    const float* W1   = (const float*)d_in[2];
    const float* a1s  = (const float*)d_in[3];
    const float* a1d  = (const float*)d_in[4];
    const float* W2   = (const float*)d_in[5];
    const float* a2s  = (const float*)d_in[6];
    const float* a2d  = (const float*)d_in[7];
    float* out = (float*)d_out;

    cudaFuncSetAttribute(gemm1_mma_kernel, cudaFuncAttributeMaxDynamicSharedMemorySize, G1_SMEM);

    // launch order keeps gemm1 at #4 (the launch ncu captures)
    init_kernel<<<NB, 256>>>((const int*)ei, W1);
    convert_hist_kernel<<<(ET + 255) / 256, 256>>>(ei);
    scan_partial_kernel<<<NB, 256>>>();
    gemm1_mma_kernel<<<(NN + 127) / 128, 256, G1_SMEM>>>(x, a1s, a1d);   // launch #4
    scan_blocks_kernel<<<1, 512>>>();
    scan_apply_kernel<<<NB, 256>>>();
    scatter_kernel<<<(ET + 255) / 256, 256>>>();
    agg1_kernel<<<(NN * 32 + 255) / 256, 256>>>();

    gemm2_kernel<<<(NN * CC + 255) / 256, 256>>>(W2, a2s, a2d);
    agg2_kernel<<<(NN * 16 + 255) / 256, 256>>>(out);
}

// round 10
// speedup vs baseline: 1.8807x; 1.1200x over previous
#include <cuda_runtime.h>
#include <cuda_bf16.h>
#include <math.h>
#include <stdint.h>

#define NN   100000
#define EE   1600000
#define ET   1700000      // EE + NN self loops
#define FIN  512
#define HD   64           // H1*D1
#define H1   8
#define D1   8
#define CC   16
#define NB   ((NN + 255) / 256)   // 391 scan blocks

// ---------------- scratch (static device memory; no allocations) ----------------
__device__ int   g_flag;
__device__ int   g_src[ET];
__device__ int   g_dst[ET];
__device__ int   g_col[ET];
__device__ int   g_counts[NN];
__device__ int   g_cursor[NN];
__device__ int   g_rowptr[NN + 1];
__device__ int   g_bsum[NB];
__device__ int   g_boff[NB];
__device__ uint2 g_wpk[HD * FIN / 2];   // W1^T packed: [n][k/2] = {hi(k),hi(k+1) | lo(k),lo(k+1)}
__device__ float g_h1[(size_t)NN * HD];
__device__ float g_h1act[(size_t)NN * HD];
__device__ float g_es1[(size_t)NN * H1];
__device__ float g_ed1[(size_t)NN * H1];
__device__ float g_h2[(size_t)NN * CC];
__device__ float g_es2[NN];
__device__ float g_ed2[NN];

// ---------------- init: zero counts + dtype detect + W1 packed hi/lo convert ----------------
__global__ __launch_bounds__(256) void init_kernel(const int* ei32, const float* __restrict__ W1) {
    int i = blockIdx.x * blockDim.x + threadIdx.x;
    if (i < NN) g_counts[i] = 0;
    if (i < HD * FIN / 2) {                 // pack pair (2kp, 2kp+1) of column n
        int n = i >> 8, kp = i & 255;
        float v0 = W1[(size_t)(2 * kp) * HD + n];
        float v1 = W1[(size_t)(2 * kp + 1) * HD + n];
        __nv_bfloat16 h0 = __float2bfloat16_rn(v0);
        __nv_bfloat16 h1 = __float2bfloat16_rn(v1);
        __nv_bfloat16 l0 = __float2bfloat16_rn(v0 - __bfloat162float(h0));
        __nv_bfloat16 l1 = __float2bfloat16_rn(v1 - __bfloat162float(h1));
        uint2 w;
        w.x = ((uint32_t)__bfloat16_as_ushort(h1) << 16) | __bfloat16_as_ushort(h0);
        w.y = ((uint32_t)__bfloat16_as_ushort(l1) << 16) | __bfloat16_as_ushort(l0);
        g_wpk[i] = w;
    }
    if (blockIdx.x == 0 && threadIdx.x < 32) {
        int lane = threadIdx.x;
        int bad = 0;
        for (int j = lane; j < 256; j += 32) {
            int k = j * 6250;
            if (ei32[2 * k + 1] != 0) bad = 1;
        }
        unsigned b = __ballot_sync(0xffffffffu, bad);
        if (lane == 0) g_flag = (b == 0) ? 1 : 0;
    }
}

// ---------------- convert + histogram in one edge pass ----------------
__global__ __launch_bounds__(256) void convert_hist_kernel(const void* ei) {
    int e = blockIdx.x * blockDim.x + threadIdx.x;
    if (e >= ET) return;
    int s, d;
    if (e < EE) {
        if (g_flag) {
            const long long* p = (const long long*)ei;
            s = (int)p[e]; d = (int)p[EE + e];
        } else {
            const int* p = (const int*)ei;
            s = p[e]; d = p[EE + e];
        }
    } else {
        s = e - EE; d = e - EE;
    }
    g_src[e] = s; g_dst[e] = d;
    atomicAdd(&g_counts[d], 1);
}

// ---------------- parallel scan ----------------
__global__ __launch_bounds__(256) void scan_partial_kernel() {
    __shared__ int wsum[8];
    int t = threadIdx.x;
    int i = blockIdx.x * 256 + t;
    int c = (i < NN) ? g_counts[i] : 0;
    int v = c;
    #pragma unroll
    for (int off = 1; off < 32; off <<= 1) v += __shfl_xor_sync(0xffffffffu, v, off);
    if ((t & 31) == 0) wsum[t >> 5] = v;
    __syncthreads();
    if (t == 0) {
        int s = 0;
        #pragma unroll
        for (int w = 0; w < 8; w++) s += wsum[w];
        g_bsum[blockIdx.x] = s;
    }
}

__global__ __launch_bounds__(512) void scan_blocks_kernel() {
    __shared__ int sh[512];
    int t = threadIdx.x;
    sh[t] = (t < NB) ? g_bsum[t] : 0;
    __syncthreads();
    for (int off = 1; off < 512; off <<= 1) {
        int v = (t >= off) ? sh[t - off] : 0;
        __syncthreads();
        sh[t] += v;
        __syncthreads();
    }
    if (t < NB) g_boff[t] = (t == 0) ? 0 : sh[t - 1];
}

__global__ __launch_bounds__(256) void scan_apply_kernel() {
    __shared__ int woff[8];
    int t = threadIdx.x, lane = t & 31, wid = t >> 5;
    int i = blockIdx.x * 256 + t;
    int c = (i < NN) ? g_counts[i] : 0;
    int incl = c;
    #pragma unroll
    for (int off = 1; off < 32; off <<= 1) {
        int v = __shfl_up_sync(0xffffffffu, incl, off);
        if (lane >= off) incl += v;
    }
    if (lane == 31) woff[wid] = incl;
    __syncthreads();
    if (t == 0) {
        int run = 0;
        #pragma unroll
        for (int w = 0; w < 8; w++) { int v = woff[w]; woff[w] = run; run += v; }
    }
    __syncthreads();
    int excl = incl - c + woff[wid] + g_boff[blockIdx.x];
    if (i < NN) { g_rowptr[i] = excl; g_cursor[i] = excl; }
    if (i == NN - 1) g_rowptr[NN] = ET;
}

__global__ __launch_bounds__(256) void scatter_kernel() {
    int e = blockIdx.x * blockDim.x + threadIdx.x;
    if (e < ET) {
        int d = g_dst[e];
        int pos = atomicAdd(&g_cursor[d], 1);
        g_col[pos] = g_src[e];
    }
}

// ---------------- GEMM1: cp.async-staged A + HMMA split-bf16 + fused es/ed ----------------
#define BKG   32                  // K per stage
#define NSTG  4                   // stages
#define ASTR  36                  // fp32 stride per A row
#define STAGE_B (128 * ASTR * 4)  // 18432 bytes
#define G1_SMEM (NSTG * STAGE_B)  // 73728 bytes

__device__ __forceinline__ void cp_async_cg(uint32_t saddr, const void* gptr, int srcsz) {
    asm volatile("cp.async.cg.shared.global [%0], [%1], 16, %2;"
                 :: "r"(saddr), "l"(gptr), "r"(srcsz));
}
__device__ __forceinline__ void cp_commit() { asm volatile("cp.async.commit_group;"); }

__device__ __forceinline__ void cvt_pair(float vx, float vy, uint32_t& hi, uint32_t& lo) {
    asm("cvt.rn.bf16x2.f32 %0, %1, %2;" : "=r"(hi) : "f"(vy), "f"(vx));
    float h0 = __uint_as_float(hi << 16);
    float h1 = __uint_as_float(hi & 0xFFFF0000u);
    float r0 = vx - h0, r1 = vy - h1;
    asm("cvt.rn.bf16x2.f32 %0, %1, %2;" : "=r"(lo) : "f"(r1), "f"(r0));
}

__device__ __forceinline__ void mma16816(float* c, const uint32_t* a, uint32_t b0, uint32_t b1) {
    asm volatile(
        "mma.sync.aligned.m16n8k16.row.col.f32.bf16.bf16.f32 "
        "{%0,%1,%2,%3}, {%4,%5,%6,%7}, {%8,%9}, {%0,%1,%2,%3};"
        : "+f"(c[0]), "+f"(c[1]), "+f"(c[2]), "+f"(c[3])
        : "r"(a[0]), "r"(a[1]), "r"(a[2]), "r"(a[3]), "r"(b0), "r"(b1));
}

__global__ __launch_bounds__(256, 2) void gemm1_mma_kernel(const float* __restrict__ x,
                                                           const float* __restrict__ a1s,
                                                           const float* __restrict__ a1d) {
    extern __shared__ float sA[];           // [NSTG][128][ASTR]
    uint32_t sbase;
    asm("{ .reg .u64 t; cvta.to.shared.u64 t, %1; cvt.u32.u64 %0, t; }" : "=r"(sbase) : "l"(sA));

    int tid = threadIdx.x;
    int wid = tid >> 5, lane = tid & 31;
    int g = lane >> 2, tc = lane & 3;
    int wm = wid & 3, wn = wid >> 2;
    int block_row = blockIdx.x * 128;
    int row_base = block_row + wm * 32;

    float acc[2][4][4];
    #pragma unroll
    for (int mt = 0; mt < 2; mt++)
        #pragma unroll
        for (int nt = 0; nt < 4; nt++)
            #pragma unroll
            for (int q = 0; q < 4; q++) acc[mt][nt][q] = 0.f;

    const int NSTEP = FIN / BKG;            // 16

    #pragma unroll
    for (int s = 0; s < NSTG - 1; s++) {    // prologue: 3 stages
        #pragma unroll
        for (int i = 0; i < 4; i++) {
            int idx = tid + 256 * i;
            int row = idx >> 3, c4 = idx & 7;
            int grow = block_row + row;
            uint32_t sa = sbase + (uint32_t)s * STAGE_B + (row * ASTR + c4 * 4) * 4;
            cp_async_cg(sa, x + (size_t)grow * FIN + s * BKG + c4 * 4,
                        (grow < NN) ? 16 : 0);
        }
        cp_commit();
    }

    for (int step = 0; step < NSTEP; step++) {
        int rem = NSTEP - 1 - step;
        if (rem >= 2) { asm volatile("cp.async.wait_group 2;"); }
        else if (rem == 1) { asm volatile("cp.async.wait_group 1;"); }
        else { asm volatile("cp.async.wait_group 0;"); }
        __syncthreads();

        int nxt = step + NSTG - 1;
        if (nxt < NSTEP) {
            int sbuf = nxt & (NSTG - 1);
            #pragma unroll
            for (int i = 0; i < 4; i++) {
                int idx = tid + 256 * i;
                int row = idx >> 3, c4 = idx & 7;
                int grow = block_row + row;
                uint32_t sa = sbase + (uint32_t)sbuf * STAGE_B + (row * ASTR + c4 * 4) * 4;
                cp_async_cg(sa, x + (size_t)grow * FIN + nxt * BKG + c4 * 4,
                            (grow < NN) ? 16 : 0);
            }
            cp_commit();
        }

        const float* sAc = sA + (step & (NSTG - 1)) * 128 * ASTR;
        #pragma unroll
        for (int ks = 0; ks < BKG / 16; ks++) {  // 2
            int kg = step * BKG + ks * 16;
            int kl = ks * 16 + tc * 2;
            uint32_t ah[2][4], al[2][4];
            #pragma unroll
            for (int mt = 0; mt < 2; mt++) {
                int lr0 = wm * 32 + mt * 16 + g;
                int lr1 = lr0 + 8;
                float2 v0 = *(const float2*)(sAc + lr0 * ASTR + kl);
                float2 v1 = *(const float2*)(sAc + lr1 * ASTR + kl);
                float2 v2 = *(const float2*)(sAc + lr0 * ASTR + kl + 8);
                float2 v3 = *(const float2*)(sAc + lr1 * ASTR + kl + 8);
                cvt_pair(v0.x, v0.y, ah[mt][0], al[mt][0]);
                cvt_pair(v1.x, v1.y, ah[mt][1], al[mt][1]);
                cvt_pair(v2.x, v2.y, ah[mt][2], al[mt][2]);
                cvt_pair(v3.x, v3.y, ah[mt][3], al[mt][3]);
            }
            // packed W: [n][k/2] uint2 {hi-pair, lo-pair}
            int kp = (kg >> 1) + tc;        // pair index of k = kg + tc*2
            #pragma unroll
            for (int nt = 0; nt < 4; nt++) {
                int n = wn * 32 + nt * 8 + g;
                const uint2* wp = g_wpk + n * (FIN / 2) + kp;
                uint2 w0 = wp[0];           // k pair (tc*2, tc*2+1)
                uint2 w1 = wp[4];           // k pair (tc*2+8, tc*2+9)
                #pragma unroll
                for (int mt = 0; mt < 2; mt++) {
                    mma16816(acc[mt][nt], ah[mt], w0.x, w1.x);
                    mma16816(acc[mt][nt], al[mt], w0.x, w1.x);
                    mma16816(acc[mt][nt], ah[mt], w0.y, w1.y);
                }
            }
        }
    }

    // ---- epilogue: write h1, fused es/ed ----
    int col_base = wn * 32;
    #pragma unroll
    for (int mt = 0; mt < 2; mt++) {
        int r0 = row_base + mt * 16 + g;
        int r1 = r0 + 8;
        #pragma unroll
        for (int nt = 0; nt < 4; nt++) {
            int col = col_base + nt * 8 + tc * 2;
            float* c = acc[mt][nt];
            if (r0 < NN) *(float2*)(g_h1 + (size_t)r0 * HD + col) = make_float2(c[0], c[1]);
            if (r1 < NN) *(float2*)(g_h1 + (size_t)r1 * HD + col) = make_float2(c[2], c[3]);
            int head = (col_base >> 3) + nt;
            float as0 = a1s[head * 8 + tc * 2], as1 = a1s[head * 8 + tc * 2 + 1];
            float ad0 = a1d[head * 8 + tc * 2], ad1 = a1d[head * 8 + tc * 2 + 1];
            float es_a = c[0] * as0 + c[1] * as1;
            float ed_a = c[0] * ad0 + c[1] * ad1;
            float es_b = c[2] * as0 + c[3] * as1;
            float ed_b = c[2] * ad0 + c[3] * ad1;
            es_a += __shfl_xor_sync(0xffffffffu, es_a, 1); es_a += __shfl_xor_sync(0xffffffffu, es_a, 2);
            ed_a += __shfl_xor_sync(0xffffffffu, ed_a, 1); ed_a += __shfl_xor_sync(0xffffffffu, ed_a, 2);
            es_b += __shfl_xor_sync(0xffffffffu, es_b, 1); es_b += __shfl_xor_sync(0xffffffffu, es_b, 2);
            ed_b += __shfl_xor_sync(0xffffffffu, ed_b, 1); ed_b += __shfl_xor_sync(0xffffffffu, ed_b, 2);
            if (tc == 0) {
                if (r0 < NN) { g_es1[(size_t)r0 * H1 + head] = es_a; g_ed1[(size_t)r0 * H1 + head] = ed_a; }
                if (r1 < NN) { g_es1[(size_t)r1 * H1 + head] = es_b; g_ed1[(size_t)r1 * H1 + head] = ed_b; }
            }
        }
    }
}

// ---------------- layer-1 aggregation: warp per dst, online softmax, ELU ----------------
__global__ __launch_bounds__(256) void agg1_kernel() {
    int warp = (blockIdx.x * blockDim.x + threadIdx.x) >> 5;
    int lane = threadIdx.x & 31;
    if (warp >= NN) return;
    int dst = warp;
    int head0 = lane >> 3;
    float edv = (lane < 8) ? g_ed1[(size_t)dst * H1 + lane] : 0.f;
    float m = -INFINITY, s = 0.f;
    float acc0 = 0.f, acc1 = 0.f;
    int beg = g_rowptr[dst], end = g_rowptr[dst + 1];
    for (int e = beg; e < end; e++) {
        int src = g_col[e];
        float scale = 1.f, w = 0.f;
        if (lane < 8) {
            float ev = g_es1[(size_t)src * H1 + lane] + edv;
            ev = ev > 0.f ? ev : 0.2f * ev;
            float nm = fmaxf(m, ev);
            scale = __expf(m - nm);
            w = __expf(ev - nm);
            m = nm;
            s = s * scale + w;
        }
        float sc0 = __shfl_sync(0xffffffffu, scale, head0);
        float w0  = __shfl_sync(0xffffffffu, w,     head0);
        float sc1 = __shfl_sync(0xffffffffu, scale, head0 + 4);
        float w1  = __shfl_sync(0xffffffffu, w,     head0 + 4);
        float hv0 = g_h1[(size_t)src * HD + lane];
        float hv1 = g_h1[(size_t)src * HD + lane + 32];
        acc0 = acc0 * sc0 + hv0 * w0;
        acc1 = acc1 * sc1 + hv1 * w1;
    }
    float s0 = __shfl_sync(0xffffffffu, s, head0);
    float s1 = __shfl_sync(0xffffffffu, s, head0 + 4);
    float o0 = acc0 / s0;
    float o1 = acc1 / s1;
    o0 = o0 > 0.f ? o0 : expm1f(o0);
    o1 = o1 > 0.f ? o1 : expm1f(o1);
    g_h1act[(size_t)dst * HD + lane] = o0;
    g_h1act[(size_t)dst * HD + lane + 32] = o1;
}

// ---------------- GEMM2 + fused es2/ed2 ----------------
__global__ __launch_bounds__(256) void gemm2_kernel(const float* __restrict__ W2,
                                                    const float* __restrict__ a2s,
                                                    const float* __restrict__ a2d) {
    __shared__ float Ws[HD * CC];
    int t = threadIdx.x;
    {
        float4 v = ((const float4*)W2)[t];
        ((float4*)Ws)[t] = v;
    }
    __syncthreads();
    int idx = blockIdx.x * 256 + t;
    if (idx >= NN * CC) return;
    int n = idx >> 4, c = idx & 15;
    const float4* h4 = (const float4*)(g_h1act + (size_t)n * HD);
    float sum = 0.f;
    #pragma unroll
    for (int j = 0; j < 16; j++) {
        float4 v = h4[j];
        sum += v.x * Ws[(4 * j + 0) * CC + c];
        sum += v.y * Ws[(4 * j + 1) * CC + c];
        sum += v.z * Ws[(4 * j + 2) * CC + c];
        sum += v.w * Ws[(4 * j + 3) * CC + c];
    }
    g_h2[idx] = sum;
    float es = sum * a2s[c];
    float ed = sum * a2d[c];
    #pragma unroll
    for (int off = 1; off < 16; off <<= 1) {
        es += __shfl_xor_sync(0xffffffffu, es, off, 16);
        ed += __shfl_xor_sync(0xffffffffu, ed, off, 16);
    }
    if (c == 0) { g_es2[n] = es; g_ed2[n] = ed; }
}

// ---------------- layer-2 aggregation + log_softmax : half-warp per dst ----------------
__global__ __launch_bounds__(256) void agg2_kernel(float* __restrict__ out) {
    int gw = (blockIdx.x * blockDim.x + threadIdx.x) >> 5;
    int lane = threadIdx.x & 31;
    int half = lane >> 4;
    int r = lane & 15;
    int dst = gw * 2 + half;
    float edv = g_ed2[dst];
    float m = -INFINITY, s = 0.f, acc = 0.f;
    int beg = g_rowptr[dst], end = g_rowptr[dst + 1];
    for (int e = beg; e < end; e++) {
        int src = g_col[e];
        float ev = g_es2[src] + edv;
        ev = ev > 0.f ? ev : 0.2f * ev;
        float nm = fmaxf(m, ev);
        float scale = __expf(m - nm);
        float w = __expf(ev - nm);
        m = nm;
        s = s * scale + w;
        acc = acc * scale + g_h2[(size_t)src * CC + r] * w;
    }
    float o = acc / s;
    float mx = o;
    #pragma unroll
    for (int off = 8; off; off >>= 1)
        mx = fmaxf(mx, __shfl_xor_sync(0xffffffffu, mx, off, 16));
    float se = __expf(o - mx);
    #pragma unroll
    for (int off = 8; off; off >>= 1)
        se += __shfl_xor_sync(0xffffffffu, se, off, 16);
    out[(size_t)dst * CC + r] = o - mx - logf(se);
}

// ---------------- launch ----------------
extern "C" void kernel_launch(void* const* d_in, const int* in_sizes, int n_in,
                              void* d_out, int out_size) {
    const float* x    = (const float*)d_in[0];
    const void*  ei   = d_in[1];
    const float* W1   = (const float*)d_in[2];
    const float* a1s  = (const float*)d_in[3];
    const float* a1d  = (const float*)d_in[4];
    const float* W2   = (const float*)d_in[5];
    const float* a2s  = (const float*)d_in[6];
    const float* a2d  = (const float*)d_in[7];
    float* out = (float*)d_out;

    cudaFuncSetAttribute(gemm1_mma_kernel, cudaFuncAttributeMaxDynamicSharedMemorySize, G1_SMEM);

    // launch order keeps gemm1 at #4 (the launch ncu captures)
    init_kernel<<<NB, 256>>>((const int*)ei, W1);
    convert_hist_kernel<<<(ET + 255) / 256, 256>>>(ei);
    scan_partial_kernel<<<NB, 256>>>();
    gemm1_mma_kernel<<<(NN + 127) / 128, 256, G1_SMEM>>>(x, a1s, a1d);   // launch #4
    scan_blocks_kernel<<<1, 512>>>();
    scan_apply_kernel<<<NB, 256>>>();
    scatter_kernel<<<(ET + 255) / 256, 256>>>();
    agg1_kernel<<<(NN * 32 + 255) / 256, 256>>>();

    gemm2_kernel<<<(NN * CC + 255) / 256, 256>>>(W2, a2s, a2d);
    agg2_kernel<<<(NN * 16 + 255) / 256, 256>>>(out);
}

// round 11
// speedup vs baseline: 1.9891x; 1.0576x over previous
#include <cuda_runtime.h>
#include <cuda_bf16.h>
#include <math.h>
#include <stdint.h>

#define NN   100000
#define EE   1600000
#define ET   1700000      // EE + NN self loops
#define FIN  512
#define HD   64           // H1*D1
#define H1   8
#define D1   8
#define CC   16
#define NB   ((NN + 255) / 256)   // 391 scan blocks

// ---------------- scratch (static device memory; no allocations) ----------------
__device__ int   g_flag;
__device__ int   g_src[ET];
__device__ int   g_dst[ET];
__device__ int   g_col[ET];
__device__ int   g_counts[NN];
__device__ int   g_cursor[NN];
__device__ int   g_rowptr[NN + 1];
__device__ int   g_bsum[NB];
__device__ int   g_boff[NB];
// W1^T in mma-fragment order: [n][ks][tc] uint4 = {hi(k0,k0+1), hi(k0+8,k0+9), lo(k0,k0+1), lo(k0+8,k0+9)}
// where k0 = ks*16 + tc*2
__device__ uint4 g_wfrag[HD * 32 * 4];
__device__ float g_h1[(size_t)NN * HD];
__device__ float g_h1act[(size_t)NN * HD];
__device__ float g_es1[(size_t)NN * H1];
__device__ float g_ed1[(size_t)NN * H1];
__device__ float g_h2[(size_t)NN * CC];
__device__ float g_es2[NN];
__device__ float g_ed2[NN];

__device__ __forceinline__ uint32_t pack_hi(float v0, float v1) {
    __nv_bfloat16 h0 = __float2bfloat16_rn(v0);
    __nv_bfloat16 h1 = __float2bfloat16_rn(v1);
    return ((uint32_t)__bfloat16_as_ushort(h1) << 16) | __bfloat16_as_ushort(h0);
}
__device__ __forceinline__ uint32_t pack_lo(float v0, float v1) {
    __nv_bfloat16 h0 = __float2bfloat16_rn(v0);
    __nv_bfloat16 h1 = __float2bfloat16_rn(v1);
    __nv_bfloat16 l0 = __float2bfloat16_rn(v0 - __bfloat162float(h0));
    __nv_bfloat16 l1 = __float2bfloat16_rn(v1 - __bfloat162float(h1));
    return ((uint32_t)__bfloat16_as_ushort(l1) << 16) | __bfloat16_as_ushort(l0);
}

// ---------------- init: zero counts + dtype detect + W1 fragment-order convert ----------------
__global__ __launch_bounds__(256) void init_kernel(const int* ei32, const float* __restrict__ W1) {
    int i = blockIdx.x * blockDim.x + threadIdx.x;
    if (i < NN) g_counts[i] = 0;
    if (i < HD * 32 * 4) {                  // 8192 fragments
        int n = i >> 7, ks = (i >> 2) & 31, tc = i & 3;
        int k0 = ks * 16 + tc * 2;
        float v0 = W1[(size_t)k0 * HD + n];
        float v1 = W1[(size_t)(k0 + 1) * HD + n];
        float v8 = W1[(size_t)(k0 + 8) * HD + n];
        float v9 = W1[(size_t)(k0 + 9) * HD + n];
        uint4 w;
        w.x = pack_hi(v0, v1);
        w.y = pack_hi(v8, v9);
        w.z = pack_lo(v0, v1);
        w.w = pack_lo(v8, v9);
        g_wfrag[i] = w;
    }
    if (blockIdx.x == 0 && threadIdx.x < 32) {
        int lane = threadIdx.x;
        int bad = 0;
        for (int j = lane; j < 256; j += 32) {
            int k = j * 6250;
            if (ei32[2 * k + 1] != 0) bad = 1;
        }
        unsigned b = __ballot_sync(0xffffffffu, bad);
        if (lane == 0) g_flag = (b == 0) ? 1 : 0;
    }
}

// ---------------- convert + histogram in one edge pass ----------------
__global__ __launch_bounds__(256) void convert_hist_kernel(const void* ei) {
    int e = blockIdx.x * blockDim.x + threadIdx.x;
    if (e >= ET) return;
    int s, d;
    if (e < EE) {
        if (g_flag) {
            const long long* p = (const long long*)ei;
            s = (int)p[e]; d = (int)p[EE + e];
        } else {
            const int* p = (const int*)ei;
            s = p[e]; d = p[EE + e];
        }
    } else {
        s = e - EE; d = e - EE;
    }
    g_src[e] = s; g_dst[e] = d;
    atomicAdd(&g_counts[d], 1);
}

// ---------------- parallel scan ----------------
__global__ __launch_bounds__(256) void scan_partial_kernel() {
    __shared__ int wsum[8];
    int t = threadIdx.x;
    int i = blockIdx.x * 256 + t;
    int c = (i < NN) ? g_counts[i] : 0;
    int v = c;
    #pragma unroll
    for (int off = 1; off < 32; off <<= 1) v += __shfl_xor_sync(0xffffffffu, v, off);
    if ((t & 31) == 0) wsum[t >> 5] = v;
    __syncthreads();
    if (t == 0) {
        int s = 0;
        #pragma unroll
        for (int w = 0; w < 8; w++) s += wsum[w];
        g_bsum[blockIdx.x] = s;
    }
}

__global__ __launch_bounds__(512) void scan_blocks_kernel() {
    __shared__ int sh[512];
    int t = threadIdx.x;
    sh[t] = (t < NB) ? g_bsum[t] : 0;
    __syncthreads();
    for (int off = 1; off < 512; off <<= 1) {
        int v = (t >= off) ? sh[t - off] : 0;
        __syncthreads();
        sh[t] += v;
        __syncthreads();
    }
    if (t < NB) g_boff[t] = (t == 0) ? 0 : sh[t - 1];
}

__global__ __launch_bounds__(256) void scan_apply_kernel() {
    __shared__ int woff[8];
    int t = threadIdx.x, lane = t & 31, wid = t >> 5;
    int i = blockIdx.x * 256 + t;
    int c = (i < NN) ? g_counts[i] : 0;
    int incl = c;
    #pragma unroll
    for (int off = 1; off < 32; off <<= 1) {
        int v = __shfl_up_sync(0xffffffffu, incl, off);
        if (lane >= off) incl += v;
    }
    if (lane == 31) woff[wid] = incl;
    __syncthreads();
    if (t == 0) {
        int run = 0;
        #pragma unroll
        for (int w = 0; w < 8; w++) { int v = woff[w]; woff[w] = run; run += v; }
    }
    __syncthreads();
    int excl = incl - c + woff[wid] + g_boff[blockIdx.x];
    if (i < NN) { g_rowptr[i] = excl; g_cursor[i] = excl; }
    if (i == NN - 1) g_rowptr[NN] = ET;
}

__global__ __launch_bounds__(256) void scatter_kernel() {
    int e = blockIdx.x * blockDim.x + threadIdx.x;
    if (e < ET) {
        int d = g_dst[e];
        int pos = atomicAdd(&g_cursor[d], 1);
        g_col[pos] = g_src[e];
    }
}

// ---------------- GEMM1: cp.async-staged A + HMMA split-bf16 + fused es/ed ----------------
#define BKG   32                  // K per stage
#define NSTG  4                   // stages
#define ASTR  36                  // fp32 stride per A row
#define STAGE_B (128 * ASTR * 4)  // 18432 bytes
#define G1_SMEM (NSTG * STAGE_B)  // 73728 bytes

__device__ __forceinline__ void cp_async_cg(uint32_t saddr, const void* gptr, int srcsz) {
    asm volatile("cp.async.cg.shared.global [%0], [%1], 16, %2;"
                 :: "r"(saddr), "l"(gptr), "r"(srcsz));
}
__device__ __forceinline__ void cp_commit() { asm volatile("cp.async.commit_group;"); }

__device__ __forceinline__ void cvt_pair(float vx, float vy, uint32_t& hi, uint32_t& lo) {
    asm("cvt.rn.bf16x2.f32 %0, %1, %2;" : "=r"(hi) : "f"(vy), "f"(vx));
    float h0 = __uint_as_float(hi << 16);
    float h1 = __uint_as_float(hi & 0xFFFF0000u);
    float r0 = vx - h0, r1 = vy - h1;
    asm("cvt.rn.bf16x2.f32 %0, %1, %2;" : "=r"(lo) : "f"(r1), "f"(r0));
}

__device__ __forceinline__ void mma16816(float* c, const uint32_t* a, uint32_t b0, uint32_t b1) {
    asm volatile(
        "mma.sync.aligned.m16n8k16.row.col.f32.bf16.bf16.f32 "
        "{%0,%1,%2,%3}, {%4,%5,%6,%7}, {%8,%9}, {%0,%1,%2,%3};"
        : "+f"(c[0]), "+f"(c[1]), "+f"(c[2]), "+f"(c[3])
        : "r"(a[0]), "r"(a[1]), "r"(a[2]), "r"(a[3]), "r"(b0), "r"(b1));
}

__global__ __launch_bounds__(256, 2) void gemm1_mma_kernel(const float* __restrict__ x,
                                                           const float* __restrict__ a1s,
                                                           const float* __restrict__ a1d) {
    extern __shared__ float sA[];           // [NSTG][128][ASTR]
    uint32_t sbase;
    asm("{ .reg .u64 t; cvta.to.shared.u64 t, %1; cvt.u32.u64 %0, t; }" : "=r"(sbase) : "l"(sA));

    int tid = threadIdx.x;
    int wid = tid >> 5, lane = tid & 31;
    int g = lane >> 2, tc = lane & 3;
    int wm = wid & 3, wn = wid >> 2;
    int block_row = blockIdx.x * 128;
    int row_base = block_row + wm * 32;

    float acc[2][4][4];
    #pragma unroll
    for (int mt = 0; mt < 2; mt++)
        #pragma unroll
        for (int nt = 0; nt < 4; nt++)
            #pragma unroll
            for (int q = 0; q < 4; q++) acc[mt][nt][q] = 0.f;

    const int NSTEP = FIN / BKG;            // 16

    #pragma unroll
    for (int s = 0; s < NSTG - 1; s++) {    // prologue: 3 stages
        #pragma unroll
        for (int i = 0; i < 4; i++) {
            int idx = tid + 256 * i;
            int row = idx >> 3, c4 = idx & 7;
            int grow = block_row + row;
            uint32_t sa = sbase + (uint32_t)s * STAGE_B + (row * ASTR + c4 * 4) * 4;
            cp_async_cg(sa, x + (size_t)grow * FIN + s * BKG + c4 * 4,
                        (grow < NN) ? 16 : 0);
        }
        cp_commit();
    }

    for (int step = 0; step < NSTEP; step++) {
        int rem = NSTEP - 1 - step;
        if (rem >= 2) { asm volatile("cp.async.wait_group 2;"); }
        else if (rem == 1) { asm volatile("cp.async.wait_group 1;"); }
        else { asm volatile("cp.async.wait_group 0;"); }
        __syncthreads();

        int nxt = step + NSTG - 1;
        if (nxt < NSTEP) {
            int sbuf = nxt & (NSTG - 1);
            #pragma unroll
            for (int i = 0; i < 4; i++) {
                int idx = tid + 256 * i;
                int row = idx >> 3, c4 = idx & 7;
                int grow = block_row + row;
                uint32_t sa = sbase + (uint32_t)sbuf * STAGE_B + (row * ASTR + c4 * 4) * 4;
                cp_async_cg(sa, x + (size_t)grow * FIN + nxt * BKG + c4 * 4,
                            (grow < NN) ? 16 : 0);
            }
            cp_commit();
        }

        const float* sAc = sA + (step & (NSTG - 1)) * 128 * ASTR;
        #pragma unroll
        for (int ks = 0; ks < BKG / 16; ks++) {  // 2
            int ksg = step * 2 + ks;            // global 16-k step index (0..31)
            int kl = ks * 16 + tc * 2;
            uint32_t ah[2][4], al[2][4];
            #pragma unroll
            for (int mt = 0; mt < 2; mt++) {
                int lr0 = wm * 32 + mt * 16 + g;
                int lr1 = lr0 + 8;
                float2 v0 = *(const float2*)(sAc + lr0 * ASTR + kl);
                float2 v1 = *(const float2*)(sAc + lr1 * ASTR + kl);
                float2 v2 = *(const float2*)(sAc + lr0 * ASTR + kl + 8);
                float2 v3 = *(const float2*)(sAc + lr1 * ASTR + kl + 8);
                cvt_pair(v0.x, v0.y, ah[mt][0], al[mt][0]);
                cvt_pair(v1.x, v1.y, ah[mt][1], al[mt][1]);
                cvt_pair(v2.x, v2.y, ah[mt][2], al[mt][2]);
                cvt_pair(v3.x, v3.y, ah[mt][3], al[mt][3]);
            }
            #pragma unroll
            for (int nt = 0; nt < 4; nt++) {
                int n = wn * 32 + nt * 8 + g;
                uint4 w = g_wfrag[(n * 32 + ksg) * 4 + tc];   // 1 LDG.128
                #pragma unroll
                for (int mt = 0; mt < 2; mt++) {
                    mma16816(acc[mt][nt], ah[mt], w.x, w.y);
                    mma16816(acc[mt][nt], al[mt], w.x, w.y);
                    mma16816(acc[mt][nt], ah[mt], w.z, w.w);
                }
            }
        }
    }

    // ---- epilogue: write h1, fused es/ed ----
    int col_base = wn * 32;
    #pragma unroll
    for (int mt = 0; mt < 2; mt++) {
        int r0 = row_base + mt * 16 + g;
        int r1 = r0 + 8;
        #pragma unroll
        for (int nt = 0; nt < 4; nt++) {
            int col = col_base + nt * 8 + tc * 2;
            float* c = acc[mt][nt];
            if (r0 < NN) *(float2*)(g_h1 + (size_t)r0 * HD + col) = make_float2(c[0], c[1]);
            if (r1 < NN) *(float2*)(g_h1 + (size_t)r1 * HD + col) = make_float2(c[2], c[3]);
            int head = (col_base >> 3) + nt;
            float as0 = a1s[head * 8 + tc * 2], as1 = a1s[head * 8 + tc * 2 + 1];
            float ad0 = a1d[head * 8 + tc * 2], ad1 = a1d[head * 8 + tc * 2 + 1];
            float es_a = c[0] * as0 + c[1] * as1;
            float ed_a = c[0] * ad0 + c[1] * ad1;
            float es_b = c[2] * as0 + c[3] * as1;
            float ed_b = c[2] * ad0 + c[3] * ad1;
            es_a += __shfl_xor_sync(0xffffffffu, es_a, 1); es_a += __shfl_xor_sync(0xffffffffu, es_a, 2);
            ed_a += __shfl_xor_sync(0xffffffffu, ed_a, 1); ed_a += __shfl_xor_sync(0xffffffffu, ed_a, 2);
            es_b += __shfl_xor_sync(0xffffffffu, es_b, 1); es_b += __shfl_xor_sync(0xffffffffu, es_b, 2);
            ed_b += __shfl_xor_sync(0xffffffffu, ed_b, 1); ed_b += __shfl_xor_sync(0xffffffffu, ed_b, 2);
            if (tc == 0) {
                if (r0 < NN) { g_es1[(size_t)r0 * H1 + head] = es_a; g_ed1[(size_t)r0 * H1 + head] = ed_a; }
                if (r1 < NN) { g_es1[(size_t)r1 * H1 + head] = es_b; g_ed1[(size_t)r1 * H1 + head] = ed_b; }
            }
        }
    }
}

// ---------------- layer-1 aggregation: warp per dst, online softmax, ELU ----------------
__global__ __launch_bounds__(256) void agg1_kernel() {
    int warp = (blockIdx.x * blockDim.x + threadIdx.x) >> 5;
    int lane = threadIdx.x & 31;
    if (warp >= NN) return;
    int dst = warp;
    int head0 = lane >> 3;
    float edv = (lane < 8) ? g_ed1[(size_t)dst * H1 + lane] : 0.f;
    float m = -INFINITY, s = 0.f;
    float acc0 = 0.f, acc1 = 0.f;
    int beg = g_rowptr[dst], end = g_rowptr[dst + 1];
    for (int e = beg; e < end; e++) {
        int src = g_col[e];
        float scale = 1.f, w = 0.f;
        if (lane < 8) {
            float ev = g_es1[(size_t)src * H1 + lane] + edv;
            ev = ev > 0.f ? ev : 0.2f * ev;
            float nm = fmaxf(m, ev);
            scale = __expf(m - nm);
            w = __expf(ev - nm);
            m = nm;
            s = s * scale + w;
        }
        float sc0 = __shfl_sync(0xffffffffu, scale, head0);
        float w0  = __shfl_sync(0xffffffffu, w,     head0);
        float sc1 = __shfl_sync(0xffffffffu, scale, head0 + 4);
        float w1  = __shfl_sync(0xffffffffu, w,     head0 + 4);
        float hv0 = g_h1[(size_t)src * HD + lane];
        float hv1 = g_h1[(size_t)src * HD + lane + 32];
        acc0 = acc0 * sc0 + hv0 * w0;
        acc1 = acc1 * sc1 + hv1 * w1;
    }
    float s0 = __shfl_sync(0xffffffffu, s, head0);
    float s1 = __shfl_sync(0xffffffffu, s, head0 + 4);
    float o0 = acc0 / s0;
    float o1 = acc1 / s1;
    o0 = o0 > 0.f ? o0 : expm1f(o0);
    o1 = o1 > 0.f ? o1 : expm1f(o1);
    g_h1act[(size_t)dst * HD + lane] = o0;
    g_h1act[(size_t)dst * HD + lane + 32] = o1;
}

// ---------------- GEMM2 + fused es2/ed2 ----------------
__global__ __launch_bounds__(256) void gemm2_kernel(const float* __restrict__ W2,
                                                    const float* __restrict__ a2s,
                                                    const float* __restrict__ a2d) {
    __shared__ float Ws[HD * CC];
    int t = threadIdx.x;
    {
        float4 v = ((const float4*)W2)[t];
        ((float4*)Ws)[t] = v;
    }
    __syncthreads();
    int idx = blockIdx.x * 256 + t;
    if (idx >= NN * CC) return;
    int n = idx >> 4, c = idx & 15;
    const float4* h4 = (const float4*)(g_h1act + (size_t)n * HD);
    float sum = 0.f;
    #pragma unroll
    for (int j = 0; j < 16; j++) {
        float4 v = h4[j];
        sum += v.x * Ws[(4 * j + 0) * CC + c];
        sum += v.y * Ws[(4 * j + 1) * CC + c];
        sum += v.z * Ws[(4 * j + 2) * CC + c];
        sum += v.w * Ws[(4 * j + 3) * CC + c];
    }
    g_h2[idx] = sum;
    float es = sum * a2s[c];
    float ed = sum * a2d[c];
    #pragma unroll
    for (int off = 1; off < 16; off <<= 1) {
        es += __shfl_xor_sync(0xffffffffu, es, off, 16);
        ed += __shfl_xor_sync(0xffffffffu, ed, off, 16);
    }
    if (c == 0) { g_es2[n] = es; g_ed2[n] = ed; }
}

// ---------------- layer-2 aggregation + log_softmax : half-warp per dst ----------------
__global__ __launch_bounds__(256) void agg2_kernel(float* __restrict__ out) {
    int gw = (blockIdx.x * blockDim.x + threadIdx.x) >> 5;
    int lane = threadIdx.x & 31;
    int half = lane >> 4;
    int r = lane & 15;
    int dst = gw * 2 + half;
    float edv = g_ed2[dst];
    float m = -INFINITY, s = 0.f, acc = 0.f;
    int beg = g_rowptr[dst], end = g_rowptr[dst + 1];
    for (int e = beg; e < end; e++) {
        int src = g_col[e];
        float ev = g_es2[src] + edv;
        ev = ev > 0.f ? ev : 0.2f * ev;
        float nm = fmaxf(m, ev);
        float scale = __expf(m - nm);
        float w = __expf(ev - nm);
        m = nm;
        s = s * scale + w;
        acc = acc * scale + g_h2[(size_t)src * CC + r] * w;
    }
    float o = acc / s;
    float mx = o;
    #pragma unroll
    for (int off = 8; off; off >>= 1)
        mx = fmaxf(mx, __shfl_xor_sync(0xffffffffu, mx, off, 16));
    float se = __expf(o - mx);
    #pragma unroll
    for (int off = 8; off; off >>= 1)
        se += __shfl_xor_sync(0xffffffffu, se, off, 16);
    out[(size_t)dst * CC + r] = o - mx - logf(se);
}

// ---------------- launch ----------------
extern "C" void kernel_launch(void* const* d_in, const int* in_sizes, int n_in,
                              void* d_out, int out_size) {
    const float* x    = (const float*)d_in[0];
    const void*  ei   = d_in[1];
    const float* W1   = (const float*)d_in[2];
    const float* a1s  = (const float*)d_in[3];
    const float* a1d  = (const float*)d_in[4];
    const float* W2   = (const float*)d_in[5];
    const float* a2s  = (const float*)d_in[6];
    const float* a2d  = (const float*)d_in[7];
    float* out = (float*)d_out;

    cudaFuncSetAttribute(gemm1_mma_kernel, cudaFuncAttributeMaxDynamicSharedMemorySize, G1_SMEM);

    // launch order keeps gemm1 at #4 (the launch ncu captures)
    init_kernel<<<NB, 256>>>((const int*)ei, W1);
    convert_hist_kernel<<<(ET + 255) / 256, 256>>>(ei);
    scan_partial_kernel<<<NB, 256>>>();
    gemm1_mma_kernel<<<(NN + 127) / 128, 256, G1_SMEM>>>(x, a1s, a1d);   // launch #4
    scan_blocks_kernel<<<1, 512>>>();
    scan_apply_kernel<<<NB, 256>>>();
    scatter_kernel<<<(ET + 255) / 256, 256>>>();
    agg1_kernel<<<(NN * 32 + 255) / 256, 256>>>();

    gemm2_kernel<<<(NN * CC + 255) / 256, 256>>>(W2, a2s, a2d);
    agg2_kernel<<<(NN * 16 + 255) / 256, 256>>>(out);
}

// round 12
// speedup vs baseline: 2.0949x; 1.0532x over previous
#include <cuda_runtime.h>
#include <cuda_bf16.h>
#include <math.h>
#include <stdint.h>

#define NN   100000
#define EE   1600000
#define ET   1700000      // EE + NN self loops
#define FIN  512
#define HD   64           // H1*D1
#define H1   8
#define D1   8
#define CC   16
#define NB   ((NN + 255) / 256)   // 391 scan blocks

// ---------------- scratch (static device memory; no allocations) ----------------
__device__ int   g_flag;
__device__ int   g_src[ET];
__device__ int   g_dst[ET];
__device__ int   g_col[ET];
__device__ int   g_counts[NN];
__device__ int   g_cursor[NN];
__device__ int   g_rowptr[NN + 1];
__device__ int   g_bsum[NB];
__device__ int   g_boff[NB];
// W1^T in mma-fragment order with K-permutation: [n][ks][tc] uint4 =
// {hi(kp,kp+1), hi(kp+2,kp+3), lo(kp,kp+1), lo(kp+2,kp+3)}, kp = ks*16 + tc*4
__device__ uint4 g_wfrag[HD * 32 * 4];
__device__ float g_h1[(size_t)NN * HD];
__device__ float g_h1act[(size_t)NN * HD];
__device__ float g_es1[(size_t)NN * H1];
__device__ float g_ed1[(size_t)NN * H1];
__device__ float g_h2[(size_t)NN * CC];
__device__ float g_es2[NN];
__device__ float g_ed2[NN];

__device__ __forceinline__ uint32_t pack_hi(float v0, float v1) {
    __nv_bfloat16 h0 = __float2bfloat16_rn(v0);
    __nv_bfloat16 h1 = __float2bfloat16_rn(v1);
    return ((uint32_t)__bfloat16_as_ushort(h1) << 16) | __bfloat16_as_ushort(h0);
}
__device__ __forceinline__ uint32_t pack_lo(float v0, float v1) {
    __nv_bfloat16 h0 = __float2bfloat16_rn(v0);
    __nv_bfloat16 h1 = __float2bfloat16_rn(v1);
    __nv_bfloat16 l0 = __float2bfloat16_rn(v0 - __bfloat162float(h0));
    __nv_bfloat16 l1 = __float2bfloat16_rn(v1 - __bfloat162float(h1));
    return ((uint32_t)__bfloat16_as_ushort(l1) << 16) | __bfloat16_as_ushort(l0);
}

// ---------------- init: zero counts + dtype detect + W1 fragment-order convert ----------------
__global__ __launch_bounds__(256) void init_kernel(const int* ei32, const float* __restrict__ W1) {
    int i = blockIdx.x * blockDim.x + threadIdx.x;
    if (i < NN) g_counts[i] = 0;
    if (i < HD * 32 * 4) {                  // 8192 fragments
        int n = i >> 7, ks = (i >> 2) & 31, tc = i & 3;
        int kp = ks * 16 + tc * 4;          // physical k base (K-permuted order)
        float v0 = W1[(size_t)kp * HD + n];
        float v1 = W1[(size_t)(kp + 1) * HD + n];
        float v2 = W1[(size_t)(kp + 2) * HD + n];
        float v3 = W1[(size_t)(kp + 3) * HD + n];
        uint4 w;
        w.x = pack_hi(v0, v1);
        w.y = pack_hi(v2, v3);
        w.z = pack_lo(v0, v1);
        w.w = pack_lo(v2, v3);
        g_wfrag[i] = w;
    }
    if (blockIdx.x == 0 && threadIdx.x < 32) {
        int lane = threadIdx.x;
        int bad = 0;
        for (int j = lane; j < 256; j += 32) {
            int k = j * 6250;
            if (ei32[2 * k + 1] != 0) bad = 1;
        }
        unsigned b = __ballot_sync(0xffffffffu, bad);
        if (lane == 0) g_flag = (b == 0) ? 1 : 0;
    }
}

// ---------------- convert + histogram in one edge pass ----------------
__global__ __launch_bounds__(256) void convert_hist_kernel(const void* ei) {
    int e = blockIdx.x * blockDim.x + threadIdx.x;
    if (e >= ET) return;
    int s, d;
    if (e < EE) {
        if (g_flag) {
            const long long* p = (const long long*)ei;
            s = (int)p[e]; d = (int)p[EE + e];
        } else {
            const int* p = (const int*)ei;
            s = p[e]; d = p[EE + e];
        }
    } else {
        s = e - EE; d = e - EE;
    }
    g_src[e] = s; g_dst[e] = d;
    atomicAdd(&g_counts[d], 1);
}

// ---------------- parallel scan ----------------
__global__ __launch_bounds__(256) void scan_partial_kernel() {
    __shared__ int wsum[8];
    int t = threadIdx.x;
    int i = blockIdx.x * 256 + t;
    int c = (i < NN) ? g_counts[i] : 0;
    int v = c;
    #pragma unroll
    for (int off = 1; off < 32; off <<= 1) v += __shfl_xor_sync(0xffffffffu, v, off);
    if ((t & 31) == 0) wsum[t >> 5] = v;
    __syncthreads();
    if (t == 0) {
        int s = 0;
        #pragma unroll
        for (int w = 0; w < 8; w++) s += wsum[w];
        g_bsum[blockIdx.x] = s;
    }
}

__global__ __launch_bounds__(512) void scan_blocks_kernel() {
    __shared__ int sh[512];
    int t = threadIdx.x;
    sh[t] = (t < NB) ? g_bsum[t] : 0;
    __syncthreads();
    for (int off = 1; off < 512; off <<= 1) {
        int v = (t >= off) ? sh[t - off] : 0;
        __syncthreads();
        sh[t] += v;
        __syncthreads();
    }
    if (t < NB) g_boff[t] = (t == 0) ? 0 : sh[t - 1];
}

__global__ __launch_bounds__(256) void scan_apply_kernel() {
    __shared__ int woff[8];
    int t = threadIdx.x, lane = t & 31, wid = t >> 5;
    int i = blockIdx.x * 256 + t;
    int c = (i < NN) ? g_counts[i] : 0;
    int incl = c;
    #pragma unroll
    for (int off = 1; off < 32; off <<= 1) {
        int v = __shfl_up_sync(0xffffffffu, incl, off);
        if (lane >= off) incl += v;
    }
    if (lane == 31) woff[wid] = incl;
    __syncthreads();
    if (t == 0) {
        int run = 0;
        #pragma unroll
        for (int w = 0; w < 8; w++) { int v = woff[w]; woff[w] = run; run += v; }
    }
    __syncthreads();
    int excl = incl - c + woff[wid] + g_boff[blockIdx.x];
    if (i < NN) { g_rowptr[i] = excl; g_cursor[i] = excl; }
    if (i == NN - 1) g_rowptr[NN] = ET;
}

__global__ __launch_bounds__(256) void scatter_kernel() {
    int e = blockIdx.x * blockDim.x + threadIdx.x;
    if (e < ET) {
        int d = g_dst[e];
        int pos = atomicAdd(&g_cursor[d], 1);
        g_col[pos] = g_src[e];
    }
}

// ---------------- GEMM1: cp.async-staged A + HMMA split-bf16 (K-permuted) + fused es/ed ----------------
#define BKG   32                  // K per stage
#define NSTG  4                   // stages
#define ASTR  48                  // fp32 stride per A row (192B; 64B mod 128 -> conflict-free LDS.128)
#define STAGE_B (128 * ASTR * 4)  // 24576 bytes
#define G1_SMEM (NSTG * STAGE_B)  // 98304 bytes

__device__ __forceinline__ void cp_async_cg(uint32_t saddr, const void* gptr, int srcsz) {
    asm volatile("cp.async.cg.shared.global [%0], [%1], 16, %2;"
                 :: "r"(saddr), "l"(gptr), "r"(srcsz));
}
__device__ __forceinline__ void cp_commit() { asm volatile("cp.async.commit_group;"); }

__device__ __forceinline__ void cvt_pair(float vx, float vy, uint32_t& hi, uint32_t& lo) {
    asm("cvt.rn.bf16x2.f32 %0, %1, %2;" : "=r"(hi) : "f"(vy), "f"(vx));
    float h0 = __uint_as_float(hi << 16);
    float h1 = __uint_as_float(hi & 0xFFFF0000u);
    float r0 = vx - h0, r1 = vy - h1;
    asm("cvt.rn.bf16x2.f32 %0, %1, %2;" : "=r"(lo) : "f"(r1), "f"(r0));
}

__device__ __forceinline__ void mma16816(float* c, const uint32_t* a, uint32_t b0, uint32_t b1) {
    asm volatile(
        "mma.sync.aligned.m16n8k16.row.col.f32.bf16.bf16.f32 "
        "{%0,%1,%2,%3}, {%4,%5,%6,%7}, {%8,%9}, {%0,%1,%2,%3};"
        : "+f"(c[0]), "+f"(c[1]), "+f"(c[2]), "+f"(c[3])
        : "r"(a[0]), "r"(a[1]), "r"(a[2]), "r"(a[3]), "r"(b0), "r"(b1));
}

__global__ __launch_bounds__(256, 2) void gemm1_mma_kernel(const float* __restrict__ x,
                                                           const float* __restrict__ a1s,
                                                           const float* __restrict__ a1d) {
    extern __shared__ float sA[];           // [NSTG][128][ASTR]
    uint32_t sbase;
    asm("{ .reg .u64 t; cvta.to.shared.u64 t, %1; cvt.u32.u64 %0, t; }" : "=r"(sbase) : "l"(sA));

    int tid = threadIdx.x;
    int wid = tid >> 5, lane = tid & 31;
    int g = lane >> 2, tc = lane & 3;
    int wm = wid & 3, wn = wid >> 2;
    int block_row = blockIdx.x * 128;
    int row_base = block_row + wm * 32;

    float acc[2][4][4];
    #pragma unroll
    for (int mt = 0; mt < 2; mt++)
        #pragma unroll
        for (int nt = 0; nt < 4; nt++)
            #pragma unroll
            for (int q = 0; q < 4; q++) acc[mt][nt][q] = 0.f;

    const int NSTEP = FIN / BKG;            // 16

    #pragma unroll
    for (int s = 0; s < NSTG - 1; s++) {    // prologue: 3 stages
        #pragma unroll
        for (int i = 0; i < 4; i++) {
            int idx = tid + 256 * i;
            int row = idx >> 3, c4 = idx & 7;
            int grow = block_row + row;
            uint32_t sa = sbase + (uint32_t)s * STAGE_B + (row * ASTR + c4 * 4) * 4;
            cp_async_cg(sa, x + (size_t)grow * FIN + s * BKG + c4 * 4,
                        (grow < NN) ? 16 : 0);
        }
        cp_commit();
    }

    for (int step = 0; step < NSTEP; step++) {
        int rem = NSTEP - 1 - step;
        if (rem >= 2) { asm volatile("cp.async.wait_group 2;"); }
        else if (rem == 1) { asm volatile("cp.async.wait_group 1;"); }
        else { asm volatile("cp.async.wait_group 0;"); }
        __syncthreads();

        int nxt = step + NSTG - 1;
        if (nxt < NSTEP) {
            int sbuf = nxt & (NSTG - 1);
            #pragma unroll
            for (int i = 0; i < 4; i++) {
                int idx = tid + 256 * i;
                int row = idx >> 3, c4 = idx & 7;
                int grow = block_row + row;
                uint32_t sa = sbase + (uint32_t)sbuf * STAGE_B + (row * ASTR + c4 * 4) * 4;
                cp_async_cg(sa, x + (size_t)grow * FIN + nxt * BKG + c4 * 4,
                            (grow < NN) ? 16 : 0);
            }
            cp_commit();
        }

        const float* sAc = sA + (step & (NSTG - 1)) * 128 * ASTR;
        #pragma unroll
        for (int ks = 0; ks < BKG / 16; ks++) {  // 2
            int ksg = step * 2 + ks;            // global 16-k step index (0..31)
            int kl = ks * 16 + tc * 4;          // physical k base for this thread
            uint32_t ah[2][4], al[2][4];
            #pragma unroll
            for (int mt = 0; mt < 2; mt++) {
                int lr0 = wm * 32 + mt * 16 + g;
                int lr1 = lr0 + 8;
                float4 v0 = *(const float4*)(sAc + lr0 * ASTR + kl);   // row g  : phys k 4tc..4tc+3
                float4 v1 = *(const float4*)(sAc + lr1 * ASTR + kl);   // row g+8
                cvt_pair(v0.x, v0.y, ah[mt][0], al[mt][0]);
                cvt_pair(v1.x, v1.y, ah[mt][1], al[mt][1]);
                cvt_pair(v0.z, v0.w, ah[mt][2], al[mt][2]);
                cvt_pair(v1.z, v1.w, ah[mt][3], al[mt][3]);
            }
            #pragma unroll
            for (int nt = 0; nt < 4; nt++) {
                int n = wn * 32 + nt * 8 + g;
                uint4 w = g_wfrag[(n * 32 + ksg) * 4 + tc];   // 1 LDG.128, same K-permutation
                #pragma unroll
                for (int mt = 0; mt < 2; mt++) {
                    mma16816(acc[mt][nt], ah[mt], w.x, w.y);
                    mma16816(acc[mt][nt], al[mt], w.x, w.y);
                    mma16816(acc[mt][nt], ah[mt], w.z, w.w);
                }
            }
        }
    }

    // ---- epilogue: write h1, fused es/ed ----
    int col_base = wn * 32;
    #pragma unroll
    for (int mt = 0; mt < 2; mt++) {
        int r0 = row_base + mt * 16 + g;
        int r1 = r0 + 8;
        #pragma unroll
        for (int nt = 0; nt < 4; nt++) {
            int col = col_base + nt * 8 + tc * 2;
            float* c = acc[mt][nt];
            if (r0 < NN) *(float2*)(g_h1 + (size_t)r0 * HD + col) = make_float2(c[0], c[1]);
            if (r1 < NN) *(float2*)(g_h1 + (size_t)r1 * HD + col) = make_float2(c[2], c[3]);
            int head = (col_base >> 3) + nt;
            float as0 = a1s[head * 8 + tc * 2], as1 = a1s[head * 8 + tc * 2 + 1];
            float ad0 = a1d[head * 8 + tc * 2], ad1 = a1d[head * 8 + tc * 2 + 1];
            float es_a = c[0] * as0 + c[1] * as1;
            float ed_a = c[0] * ad0 + c[1] * ad1;
            float es_b = c[2] * as0 + c[3] * as1;
            float ed_b = c[2] * ad0 + c[3] * ad1;
            es_a += __shfl_xor_sync(0xffffffffu, es_a, 1); es_a += __shfl_xor_sync(0xffffffffu, es_a, 2);
            ed_a += __shfl_xor_sync(0xffffffffu, ed_a, 1); ed_a += __shfl_xor_sync(0xffffffffu, ed_a, 2);
            es_b += __shfl_xor_sync(0xffffffffu, es_b, 1); es_b += __shfl_xor_sync(0xffffffffu, es_b, 2);
            ed_b += __shfl_xor_sync(0xffffffffu, ed_b, 1); ed_b += __shfl_xor_sync(0xffffffffu, ed_b, 2);
            if (tc == 0) {
                if (r0 < NN) { g_es1[(size_t)r0 * H1 + head] = es_a; g_ed1[(size_t)r0 * H1 + head] = ed_a; }
                if (r1 < NN) { g_es1[(size_t)r1 * H1 + head] = es_b; g_ed1[(size_t)r1 * H1 + head] = ed_b; }
            }
        }
    }
}

// ---------------- layer-1 aggregation: warp per dst, online softmax, ELU ----------------
// lane holds h1 dims (2*lane, 2*lane+1), both in head lane>>2.
__global__ __launch_bounds__(256) void agg1_kernel() {
    int warp = (blockIdx.x * blockDim.x + threadIdx.x) >> 5;
    int lane = threadIdx.x & 31;
    if (warp >= NN) return;
    int dst = warp;
    int myhead = lane >> 2;
    float edv = (lane < 8) ? g_ed1[(size_t)dst * H1 + lane] : 0.f;
    float m = -INFINITY, s = 0.f;
    float acc0 = 0.f, acc1 = 0.f;
    int beg = g_rowptr[dst], end = g_rowptr[dst + 1];
    for (int e = beg; e < end; e++) {
        int src = g_col[e];
        float scale = 1.f, w = 0.f;
        if (lane < 8) {
            float ev = g_es1[(size_t)src * H1 + lane] + edv;
            ev = ev > 0.f ? ev : 0.2f * ev;
            float nm = fmaxf(m, ev);
            scale = __expf(m - nm);
            w = __expf(ev - nm);
            m = nm;
            s = s * scale + w;
        }
        float sc = __shfl_sync(0xffffffffu, scale, myhead);
        float ww = __shfl_sync(0xffffffffu, w,     myhead);
        float2 hv = *(const float2*)(g_h1 + (size_t)src * HD + lane * 2);
        acc0 = acc0 * sc + hv.x * ww;
        acc1 = acc1 * sc + hv.y * ww;
    }
    float sh = __shfl_sync(0xffffffffu, s, myhead);
    float o0 = acc0 / sh;
    float o1 = acc1 / sh;
    o0 = o0 > 0.f ? o0 : expm1f(o0);
    o1 = o1 > 0.f ? o1 : expm1f(o1);
    *(float2*)(g_h1act + (size_t)dst * HD + lane * 2) = make_float2(o0, o1);
}

// ---------------- GEMM2 + fused es2/ed2 ----------------
__global__ __launch_bounds__(256) void gemm2_kernel(const float* __restrict__ W2,
                                                    const float* __restrict__ a2s,
                                                    const float* __restrict__ a2d) {
    __shared__ float Ws[HD * CC];
    int t = threadIdx.x;
    {
        float4 v = ((const float4*)W2)[t];
        ((float4*)Ws)[t] = v;
    }
    __syncthreads();
    int idx = blockIdx.x * 256 + t;
    if (idx >= NN * CC) return;
    int n = idx >> 4, c = idx & 15;
    const float4* h4 = (const float4*)(g_h1act + (size_t)n * HD);
    float sum = 0.f;
    #pragma unroll
    for (int j = 0; j < 16; j++) {
        float4 v = h4[j];
        sum += v.x * Ws[(4 * j + 0) * CC + c];
        sum += v.y * Ws[(4 * j + 1) * CC + c];
        sum += v.z * Ws[(4 * j + 2) * CC + c];
        sum += v.w * Ws[(4 * j + 3) * CC + c];
    }
    g_h2[idx] = sum;
    float es = sum * a2s[c];
    float ed = sum * a2d[c];
    #pragma unroll
    for (int off = 1; off < 16; off <<= 1) {
        es += __shfl_xor_sync(0xffffffffu, es, off, 16);
        ed += __shfl_xor_sync(0xffffffffu, ed, off, 16);
    }
    if (c == 0) { g_es2[n] = es; g_ed2[n] = ed; }
}

// ---------------- layer-2 aggregation + log_softmax : half-warp per dst ----------------
__global__ __launch_bounds__(256) void agg2_kernel(float* __restrict__ out) {
    int gw = (blockIdx.x * blockDim.x + threadIdx.x) >> 5;
    int lane = threadIdx.x & 31;
    int half = lane >> 4;
    int r = lane & 15;
    int dst = gw * 2 + half;
    float edv = g_ed2[dst];
    float m = -INFINITY, s = 0.f, acc = 0.f;
    int beg = g_rowptr[dst], end = g_rowptr[dst + 1];
    for (int e = beg; e < end; e++) {
        int src = g_col[e];
        float ev = g_es2[src] + edv;
        ev = ev > 0.f ? ev : 0.2f * ev;
        float nm = fmaxf(m, ev);
        float scale = __expf(m - nm);
        float w = __expf(ev - nm);
        m = nm;
        s = s * scale + w;
        acc = acc * scale + g_h2[(size_t)src * CC + r] * w;
    }
    float o = acc / s;
    float mx = o;
    #pragma unroll
    for (int off = 8; off; off >>= 1)
        mx = fmaxf(mx, __shfl_xor_sync(0xffffffffu, mx, off, 16));
    float se = __expf(o - mx);
    #pragma unroll
    for (int off = 8; off; off >>= 1)
        se += __shfl_xor_sync(0xffffffffu, se, off, 16);
    out[(size_t)dst * CC + r] = o - mx - logf(se);
}

// ---------------- launch ----------------
extern "C" void kernel_launch(void* const* d_in, const int* in_sizes, int n_in,
                              void* d_out, int out_size) {
    const float* x    = (const float*)d_in[0];
    const void*  ei   = d_in[1];
    const float* W1   = (const float*)d_in[2];
    const float* a1s  = (const float*)d_in[3];
    const float* a1d  = (const float*)d_in[4];
    const float* W2   = (const float*)d_in[5];
    const float* a2s  = (const float*)d_in[6];
    const float* a2d  = (const float*)d_in[7];
    float* out = (float*)d_out;

    cudaFuncSetAttribute(gemm1_mma_kernel, cudaFuncAttributeMaxDynamicSharedMemorySize, G1_SMEM);

    // launch order keeps gemm1 at #4 (the launch ncu captures)
    init_kernel<<<NB, 256>>>((const int*)ei, W1);
    convert_hist_kernel<<<(ET + 255) / 256, 256>>>(ei);
    scan_partial_kernel<<<NB, 256>>>();
    gemm1_mma_kernel<<<(NN + 127) / 128, 256, G1_SMEM>>>(x, a1s, a1d);   // launch #4
    scan_blocks_kernel<<<1, 512>>>();
    scan_apply_kernel<<<NB, 256>>>();
    scatter_kernel<<<(ET + 255) / 256, 256>>>();
    agg1_kernel<<<(NN * 32 + 255) / 256, 256>>>();

    gemm2_kernel<<<(NN * CC + 255) / 256, 256>>>(W2, a2s, a2d);
    agg2_kernel<<<(NN * 16 + 255) / 256, 256>>>(out);
}

// round 13
// speedup vs baseline: 2.2901x; 1.0932x over previous
#include <cuda_runtime.h>
#include <cuda_bf16.h>
#include <math.h>
#include <stdint.h>

#define NN   100000
#define EE   1600000
#define ET   1700000      // EE + NN self loops
#define FIN  512
#define HD   64           // H1*D1
#define H1   8
#define D1   8
#define CC   16
#define NB   ((NN + 255) / 256)   // 391 scan blocks

// ---------------- scratch (static device memory; no allocations) ----------------
__device__ int   g_flag;
__device__ int   g_src[ET];
__device__ int   g_dst[ET];
__device__ int   g_col[ET];
__device__ int   g_counts[NN];
__device__ int   g_cursor[NN];
__device__ int   g_rowptr[NN + 1];
__device__ int   g_bsum[NB];
__device__ int   g_boff[NB];
// W1^T in mma-fragment order with K-permutation: [n][ks][tc] uint4 =
// {hi(kp,kp+1), hi(kp+2,kp+3), lo(kp,kp+1), lo(kp+2,kp+3)}, kp = ks*16 + tc*4
__device__ uint4 g_wfrag[HD * 32 * 4];
__device__ float g_h1[(size_t)NN * HD];
__device__ float g_h1act[(size_t)NN * HD];
__device__ float g_es1[(size_t)NN * H1];
__device__ float g_ed1[(size_t)NN * H1];
__device__ float g_h2[(size_t)NN * CC];
__device__ float g_es2[NN];
__device__ float g_ed2[NN];

__device__ __forceinline__ uint32_t pack_hi(float v0, float v1) {
    __nv_bfloat16 h0 = __float2bfloat16_rn(v0);
    __nv_bfloat16 h1 = __float2bfloat16_rn(v1);
    return ((uint32_t)__bfloat16_as_ushort(h1) << 16) | __bfloat16_as_ushort(h0);
}
__device__ __forceinline__ uint32_t pack_lo(float v0, float v1) {
    __nv_bfloat16 h0 = __float2bfloat16_rn(v0);
    __nv_bfloat16 h1 = __float2bfloat16_rn(v1);
    __nv_bfloat16 l0 = __float2bfloat16_rn(v0 - __bfloat162float(h0));
    __nv_bfloat16 l1 = __float2bfloat16_rn(v1 - __bfloat162float(h1));
    return ((uint32_t)__bfloat16_as_ushort(l1) << 16) | __bfloat16_as_ushort(l0);
}

// ---------------- init: zero counts + dtype detect + W1 fragment-order convert ----------------
__global__ __launch_bounds__(256) void init_kernel(const int* ei32, const float* __restrict__ W1) {
    int i = blockIdx.x * blockDim.x + threadIdx.x;
    if (i < NN) g_counts[i] = 0;
    if (i < HD * 32 * 4) {                  // 8192 fragments
        int n = i >> 7, ks = (i >> 2) & 31, tc = i & 3;
        int kp = ks * 16 + tc * 4;          // physical k base (K-permuted order)
        float v0 = W1[(size_t)kp * HD + n];
        float v1 = W1[(size_t)(kp + 1) * HD + n];
        float v2 = W1[(size_t)(kp + 2) * HD + n];
        float v3 = W1[(size_t)(kp + 3) * HD + n];
        uint4 w;
        w.x = pack_hi(v0, v1);
        w.y = pack_hi(v2, v3);
        w.z = pack_lo(v0, v1);
        w.w = pack_lo(v2, v3);
        g_wfrag[i] = w;
    }
    if (blockIdx.x == 0 && threadIdx.x < 32) {
        int lane = threadIdx.x;
        int bad = 0;
        for (int j = lane; j < 256; j += 32) {
            int k = j * 6250;
            if (ei32[2 * k + 1] != 0) bad = 1;
        }
        unsigned b = __ballot_sync(0xffffffffu, bad);
        if (lane == 0) g_flag = (b == 0) ? 1 : 0;
    }
}

// ---------------- convert + histogram in one edge pass ----------------
__global__ __launch_bounds__(256) void convert_hist_kernel(const void* ei) {
    int e = blockIdx.x * blockDim.x + threadIdx.x;
    if (e >= ET) return;
    int s, d;
    if (e < EE) {
        if (g_flag) {
            const long long* p = (const long long*)ei;
            s = (int)p[e]; d = (int)p[EE + e];
        } else {
            const int* p = (const int*)ei;
            s = p[e]; d = p[EE + e];
        }
    } else {
        s = e - EE; d = e - EE;
    }
    g_src[e] = s; g_dst[e] = d;
    atomicAdd(&g_counts[d], 1);
}

// ---------------- parallel scan ----------------
__global__ __launch_bounds__(256) void scan_partial_kernel() {
    __shared__ int wsum[8];
    int t = threadIdx.x;
    int i = blockIdx.x * 256 + t;
    int c = (i < NN) ? g_counts[i] : 0;
    int v = c;
    #pragma unroll
    for (int off = 1; off < 32; off <<= 1) v += __shfl_xor_sync(0xffffffffu, v, off);
    if ((t & 31) == 0) wsum[t >> 5] = v;
    __syncthreads();
    if (t == 0) {
        int s = 0;
        #pragma unroll
        for (int w = 0; w < 8; w++) s += wsum[w];
        g_bsum[blockIdx.x] = s;
    }
}

__global__ __launch_bounds__(512) void scan_blocks_kernel() {
    __shared__ int sh[512];
    int t = threadIdx.x;
    sh[t] = (t < NB) ? g_bsum[t] : 0;
    __syncthreads();
    for (int off = 1; off < 512; off <<= 1) {
        int v = (t >= off) ? sh[t - off] : 0;
        __syncthreads();
        sh[t] += v;
        __syncthreads();
    }
    if (t < NB) g_boff[t] = (t == 0) ? 0 : sh[t - 1];
}

__global__ __launch_bounds__(256) void scan_apply_kernel() {
    __shared__ int woff[8];
    int t = threadIdx.x, lane = t & 31, wid = t >> 5;
    int i = blockIdx.x * 256 + t;
    int c = (i < NN) ? g_counts[i] : 0;
    int incl = c;
    #pragma unroll
    for (int off = 1; off < 32; off <<= 1) {
        int v = __shfl_up_sync(0xffffffffu, incl, off);
        if (lane >= off) incl += v;
    }
    if (lane == 31) woff[wid] = incl;
    __syncthreads();
    if (t == 0) {
        int run = 0;
        #pragma unroll
        for (int w = 0; w < 8; w++) { int v = woff[w]; woff[w] = run; run += v; }
    }
    __syncthreads();
    int excl = incl - c + woff[wid] + g_boff[blockIdx.x];
    if (i < NN) { g_rowptr[i] = excl; g_cursor[i] = excl; }
    if (i == NN - 1) g_rowptr[NN] = ET;
}

__global__ __launch_bounds__(256) void scatter_kernel() {
    int e = blockIdx.x * blockDim.x + threadIdx.x;
    if (e < ET) {
        int d = g_dst[e];
        int pos = atomicAdd(&g_cursor[d], 1);
        g_col[pos] = g_src[e];
    }
}

// ---------------- GEMM1: cp.async-staged A + HMMA split-bf16 (K-permuted) + fused es/ed ----------------
#define BKG   32                  // K per stage
#define NSTG  4                   // stages
#define ASTR  48                  // fp32 stride per A row (192B; 64B mod 128 -> conflict-free LDS.128)
#define STAGE_B (128 * ASTR * 4)  // 24576 bytes
#define G1_SMEM (NSTG * STAGE_B)  // 98304 bytes

__device__ __forceinline__ void cp_async_cg(uint32_t saddr, const void* gptr, int srcsz) {
    asm volatile("cp.async.cg.shared.global [%0], [%1], 16, %2;"
                 :: "r"(saddr), "l"(gptr), "r"(srcsz));
}
__device__ __forceinline__ void cp_commit() { asm volatile("cp.async.commit_group;"); }

__device__ __forceinline__ void cvt_pair(float vx, float vy, uint32_t& hi, uint32_t& lo) {
    asm("cvt.rn.bf16x2.f32 %0, %1, %2;" : "=r"(hi) : "f"(vy), "f"(vx));
    float h0 = __uint_as_float(hi << 16);
    float h1 = __uint_as_float(hi & 0xFFFF0000u);
    float r0 = vx - h0, r1 = vy - h1;
    asm("cvt.rn.bf16x2.f32 %0, %1, %2;" : "=r"(lo) : "f"(r1), "f"(r0));
}

__device__ __forceinline__ void mma16816(float* c, const uint32_t* a, uint32_t b0, uint32_t b1) {
    asm volatile(
        "mma.sync.aligned.m16n8k16.row.col.f32.bf16.bf16.f32 "
        "{%0,%1,%2,%3}, {%4,%5,%6,%7}, {%8,%9}, {%0,%1,%2,%3};"
        : "+f"(c[0]), "+f"(c[1]), "+f"(c[2]), "+f"(c[3])
        : "r"(a[0]), "r"(a[1]), "r"(a[2]), "r"(a[3]), "r"(b0), "r"(b1));
}

__global__ __launch_bounds__(256, 2) void gemm1_mma_kernel(const float* __restrict__ x,
                                                           const float* __restrict__ a1s,
                                                           const float* __restrict__ a1d) {
    extern __shared__ float sA[];           // [NSTG][128][ASTR]
    uint32_t sbase;
    asm("{ .reg .u64 t; cvta.to.shared.u64 t, %1; cvt.u32.u64 %0, t; }" : "=r"(sbase) : "l"(sA));

    int tid = threadIdx.x;
    int wid = tid >> 5, lane = tid & 31;
    int g = lane >> 2, tc = lane & 3;
    int wm = wid & 3, wn = wid >> 2;
    int block_row = blockIdx.x * 128;
    int row_base = block_row + wm * 32;

    float acc[2][4][4];
    #pragma unroll
    for (int mt = 0; mt < 2; mt++)
        #pragma unroll
        for (int nt = 0; nt < 4; nt++)
            #pragma unroll
            for (int q = 0; q < 4; q++) acc[mt][nt][q] = 0.f;

    const int NSTEP = FIN / BKG;            // 16

    #pragma unroll
    for (int s = 0; s < NSTG - 1; s++) {    // prologue: 3 stages
        #pragma unroll
        for (int i = 0; i < 4; i++) {
            int idx = tid + 256 * i;
            int row = idx >> 3, c4 = idx & 7;
            int grow = block_row + row;
            uint32_t sa = sbase + (uint32_t)s * STAGE_B + (row * ASTR + c4 * 4) * 4;
            cp_async_cg(sa, x + (size_t)grow * FIN + s * BKG + c4 * 4,
                        (grow < NN) ? 16 : 0);
        }
        cp_commit();
    }

    for (int step = 0; step < NSTEP; step++) {
        int rem = NSTEP - 1 - step;
        if (rem >= 2) { asm volatile("cp.async.wait_group 2;"); }
        else if (rem == 1) { asm volatile("cp.async.wait_group 1;"); }
        else { asm volatile("cp.async.wait_group 0;"); }
        __syncthreads();

        int nxt = step + NSTG - 1;
        if (nxt < NSTEP) {
            int sbuf = nxt & (NSTG - 1);
            #pragma unroll
            for (int i = 0; i < 4; i++) {
                int idx = tid + 256 * i;
                int row = idx >> 3, c4 = idx & 7;
                int grow = block_row + row;
                uint32_t sa = sbase + (uint32_t)sbuf * STAGE_B + (row * ASTR + c4 * 4) * 4;
                cp_async_cg(sa, x + (size_t)grow * FIN + nxt * BKG + c4 * 4,
                            (grow < NN) ? 16 : 0);
            }
            cp_commit();
        }

        const float* sAc = sA + (step & (NSTG - 1)) * 128 * ASTR;
        #pragma unroll
        for (int ks = 0; ks < BKG / 16; ks++) {  // 2
            int ksg = step * 2 + ks;            // global 16-k step index (0..31)
            int kl = ks * 16 + tc * 4;          // physical k base for this thread
            uint32_t ah[2][4], al[2][4];
            #pragma unroll
            for (int mt = 0; mt < 2; mt++) {
                int lr0 = wm * 32 + mt * 16 + g;
                int lr1 = lr0 + 8;
                float4 v0 = *(const float4*)(sAc + lr0 * ASTR + kl);   // row g  : phys k 4tc..4tc+3
                float4 v1 = *(const float4*)(sAc + lr1 * ASTR + kl);   // row g+8
                cvt_pair(v0.x, v0.y, ah[mt][0], al[mt][0]);
                cvt_pair(v1.x, v1.y, ah[mt][1], al[mt][1]);
                cvt_pair(v0.z, v0.w, ah[mt][2], al[mt][2]);
                cvt_pair(v1.z, v1.w, ah[mt][3], al[mt][3]);
            }
            #pragma unroll
            for (int nt = 0; nt < 4; nt++) {
                int n = wn * 32 + nt * 8 + g;
                uint4 w = g_wfrag[(n * 32 + ksg) * 4 + tc];   // 1 LDG.128, same K-permutation
                #pragma unroll
                for (int mt = 0; mt < 2; mt++) {
                    mma16816(acc[mt][nt], ah[mt], w.x, w.y);
                    mma16816(acc[mt][nt], al[mt], w.x, w.y);
                    mma16816(acc[mt][nt], ah[mt], w.z, w.w);
                }
            }
        }
    }

    // ---- epilogue: write h1, fused es/ed ----
    int col_base = wn * 32;
    #pragma unroll
    for (int mt = 0; mt < 2; mt++) {
        int r0 = row_base + mt * 16 + g;
        int r1 = r0 + 8;
        #pragma unroll
        for (int nt = 0; nt < 4; nt++) {
            int col = col_base + nt * 8 + tc * 2;
            float* c = acc[mt][nt];
            if (r0 < NN) *(float2*)(g_h1 + (size_t)r0 * HD + col) = make_float2(c[0], c[1]);
            if (r1 < NN) *(float2*)(g_h1 + (size_t)r1 * HD + col) = make_float2(c[2], c[3]);
            int head = (col_base >> 3) + nt;
            float as0 = a1s[head * 8 + tc * 2], as1 = a1s[head * 8 + tc * 2 + 1];
            float ad0 = a1d[head * 8 + tc * 2], ad1 = a1d[head * 8 + tc * 2 + 1];
            float es_a = c[0] * as0 + c[1] * as1;
            float ed_a = c[0] * ad0 + c[1] * ad1;
            float es_b = c[2] * as0 + c[3] * as1;
            float ed_b = c[2] * ad0 + c[3] * ad1;
            es_a += __shfl_xor_sync(0xffffffffu, es_a, 1); es_a += __shfl_xor_sync(0xffffffffu, es_a, 2);
            ed_a += __shfl_xor_sync(0xffffffffu, ed_a, 1); ed_a += __shfl_xor_sync(0xffffffffu, ed_a, 2);
            es_b += __shfl_xor_sync(0xffffffffu, es_b, 1); es_b += __shfl_xor_sync(0xffffffffu, es_b, 2);
            ed_b += __shfl_xor_sync(0xffffffffu, ed_b, 1); ed_b += __shfl_xor_sync(0xffffffffu, ed_b, 2);
            if (tc == 0) {
                if (r0 < NN) { g_es1[(size_t)r0 * H1 + head] = es_a; g_ed1[(size_t)r0 * H1 + head] = ed_a; }
                if (r1 < NN) { g_es1[(size_t)r1 * H1 + head] = es_b; g_ed1[(size_t)r1 * H1 + head] = ed_b; }
            }
        }
    }
}

// ---------------- layer-1 aggregation: warp/dst, per-lane softmax, depth-2 prefetch ----------------
// lane holds h1 dims (2*lane, 2*lane+1) of head lane>>2; every lane keeps its own (m,s).
__global__ __launch_bounds__(256) void agg1_kernel() {
    int warp = (blockIdx.x * blockDim.x + threadIdx.x) >> 5;
    int lane = threadIdx.x & 31;
    if (warp >= NN) return;
    int dst = warp;
    int myhead = lane >> 2;
    float edv = g_ed1[(size_t)dst * H1 + myhead];
    float m = -INFINITY, s = 0.f;
    float acc0 = 0.f, acc1 = 0.f;
    int beg = g_rowptr[dst], end = g_rowptr[dst + 1];
    if (beg >= end) {   // cannot happen (self loop) but keep safe
        *(float2*)(g_h1act + (size_t)dst * HD + lane * 2) = make_float2(0.f, 0.f);
        return;
    }
    int s0 = g_col[beg];
    int s1 = (beg + 1 < end) ? g_col[beg + 1] : s0;
    float es_c = g_es1[(size_t)s0 * H1 + myhead];
    float2 hv_c = *(const float2*)(g_h1 + (size_t)s0 * HD + lane * 2);
    for (int e = beg; e < end; e++) {
        int s2 = (e + 2 < end) ? g_col[e + 2] : s1;
        float es_n = g_es1[(size_t)s1 * H1 + myhead];
        float2 hv_n = *(const float2*)(g_h1 + (size_t)s1 * HD + lane * 2);
        float ev = es_c + edv;
        ev = ev > 0.f ? ev : 0.2f * ev;
        float nm = fmaxf(m, ev);
        float sc = __expf(m - nm);
        float w  = __expf(ev - nm);
        m = nm;
        s = s * sc + w;
        acc0 = acc0 * sc + hv_c.x * w;
        acc1 = acc1 * sc + hv_c.y * w;
        es_c = es_n; hv_c = hv_n;
        s1 = s2;
    }
    float o0 = acc0 / s;
    float o1 = acc1 / s;
    o0 = o0 > 0.f ? o0 : expm1f(o0);
    o1 = o1 > 0.f ? o1 : expm1f(o1);
    *(float2*)(g_h1act + (size_t)dst * HD + lane * 2) = make_float2(o0, o1);
}

// ---------------- GEMM2 + fused es2/ed2 ----------------
__global__ __launch_bounds__(256) void gemm2_kernel(const float* __restrict__ W2,
                                                    const float* __restrict__ a2s,
                                                    const float* __restrict__ a2d) {
    __shared__ float Ws[HD * CC];
    int t = threadIdx.x;
    {
        float4 v = ((const float4*)W2)[t];
        ((float4*)Ws)[t] = v;
    }
    __syncthreads();
    int idx = blockIdx.x * 256 + t;
    if (idx >= NN * CC) return;
    int n = idx >> 4, c = idx & 15;
    const float4* h4 = (const float4*)(g_h1act + (size_t)n * HD);
    float sum = 0.f;
    #pragma unroll
    for (int j = 0; j < 16; j++) {
        float4 v = h4[j];
        sum += v.x * Ws[(4 * j + 0) * CC + c];
        sum += v.y * Ws[(4 * j + 1) * CC + c];
        sum += v.z * Ws[(4 * j + 2) * CC + c];
        sum += v.w * Ws[(4 * j + 3) * CC + c];
    }
    g_h2[idx] = sum;
    float es = sum * a2s[c];
    float ed = sum * a2d[c];
    #pragma unroll
    for (int off = 1; off < 16; off <<= 1) {
        es += __shfl_xor_sync(0xffffffffu, es, off, 16);
        ed += __shfl_xor_sync(0xffffffffu, ed, off, 16);
    }
    if (c == 0) { g_es2[n] = es; g_ed2[n] = ed; }
}

// ---------------- layer-2 aggregation + log_softmax : half-warp/dst, depth-2 prefetch ----------------
__global__ __launch_bounds__(256) void agg2_kernel(float* __restrict__ out) {
    int gw = (blockIdx.x * blockDim.x + threadIdx.x) >> 5;
    int lane = threadIdx.x & 31;
    int half = lane >> 4;
    int r = lane & 15;
    int dst = gw * 2 + half;
    float edv = g_ed2[dst];
    float m = -INFINITY, s = 0.f, acc = 0.f;
    int beg = g_rowptr[dst], end = g_rowptr[dst + 1];
    int s0 = g_col[beg];
    int s1 = (beg + 1 < end) ? g_col[beg + 1] : s0;
    float es_c = g_es2[s0];
    float hv_c = g_h2[(size_t)s0 * CC + r];
    for (int e = beg; e < end; e++) {
        int s2 = (e + 2 < end) ? g_col[e + 2] : s1;
        float es_n = g_es2[s1];
        float hv_n = g_h2[(size_t)s1 * CC + r];
        float ev = es_c + edv;
        ev = ev > 0.f ? ev : 0.2f * ev;
        float nm = fmaxf(m, ev);
        float sc = __expf(m - nm);
        float w  = __expf(ev - nm);
        m = nm;
        s = s * sc + w;
        acc = acc * sc + hv_c * w;
        es_c = es_n; hv_c = hv_n;
        s1 = s2;
    }
    float o = acc / s;
    float mx = o;
    #pragma unroll
    for (int off = 8; off; off >>= 1)
        mx = fmaxf(mx, __shfl_xor_sync(0xffffffffu, mx, off, 16));
    float se = __expf(o - mx);
    #pragma unroll
    for (int off = 8; off; off >>= 1)
        se += __shfl_xor_sync(0xffffffffu, se, off, 16);
    out[(size_t)dst * CC + r] = o - mx - logf(se);
}

// ---------------- launch ----------------
extern "C" void kernel_launch(void* const* d_in, const int* in_sizes, int n_in,
                              void* d_out, int out_size) {
    const float* x    = (const float*)d_in[0];
    const void*  ei   = d_in[1];
    const float* W1   = (const float*)d_in[2];
    const float* a1s  = (const float*)d_in[3];
    const float* a1d  = (const float*)d_in[4];
    const float* W2   = (const float*)d_in[5];
    const float* a2s  = (const float*)d_in[6];
    const float* a2d  = (const float*)d_in[7];
    float* out = (float*)d_out;

    cudaFuncSetAttribute(gemm1_mma_kernel, cudaFuncAttributeMaxDynamicSharedMemorySize, G1_SMEM);

    // launch order keeps gemm1 at #4 (the launch ncu captures)
    init_kernel<<<NB, 256>>>((const int*)ei, W1);
    convert_hist_kernel<<<(ET + 255) / 256, 256>>>(ei);
    scan_partial_kernel<<<NB, 256>>>();
    gemm1_mma_kernel<<<(NN + 127) / 128, 256, G1_SMEM>>>(x, a1s, a1d);   // launch #4
    scan_blocks_kernel<<<1, 512>>>();
    scan_apply_kernel<<<NB, 256>>>();
    scatter_kernel<<<(ET + 255) / 256, 256>>>();
    agg1_kernel<<<(NN * 32 + 255) / 256, 256>>>();

    gemm2_kernel<<<(NN * CC + 255) / 256, 256>>>(W2, a2s, a2d);
    agg2_kernel<<<(NN * 16 + 255) / 256, 256>>>(out);
}